// round 1
// baseline (speedup 1.0000x reference)
#include <cuda_runtime.h>
#include <math.h>

#define BSZ   65536
#define BLK   512
#define CUdim 256
#define TAPS  100
#define EPSf  1e-5f

// ---------------- scratch (one big device global; no allocations) ----------
// offsets in floats
#define OFF_T    0ull                          // t  [BSZ*BLK]
#define OFF_Y    (OFF_T  + (size_t)BSZ*BLK)    // y  [BSZ*CU]
#define OFF_D    (OFF_Y  + (size_t)BSZ*CUdim)  // d  [BSZ*BLK]
#define OFF_S    (OFF_D  + (size_t)BSZ*BLK)    // s  [BSZ]
#define OFF_PS   (OFF_S  + (size_t)BSZ)        // col-sum partials [BLK*512]
#define OFF_PQ   (OFF_PS + (size_t)BLK*512)    // col-sq  partials [BLK*512]
#define OFF_AL   (OFF_PQ + (size_t)BLK*512)    // alpha [BLK]
#define OFF_BE   (OFF_AL + BLK)                // beta  [BLK]
#define OFF_W2F  (OFF_BE + BLK)                // W2f [CU*BLK]
#define OFF_B2F  (OFF_W2F + (size_t)CUdim*BLK) // b2f [CU]
#define OFF_C3   (OFF_B2F + CUdim)             // c3  [BLK]
#define OFF_NC   (OFF_C3 + BLK)                // nc  [CU]
#define OFF_W4F  (OFF_NC + CUdim)              // W4f [BLK*BLK]
#define OFF_B4F  (OFF_W4F + (size_t)BLK*BLK)   // b4f [BLK]
#define SCRATCH_TOTAL (OFF_B4F + BLK)

__device__ float g_scratch[SCRATCH_TOTAL];

// ---------------- noise FIR kernel ----------------------------------------
__global__ void k_noise(const float* __restrict__ noise,
                        const float* __restrict__ fir,
                        float* __restrict__ nc_out,
                        float* __restrict__ tail)
{
    __shared__ float v[CUdim];
    int t = threadIdx.x;
    // noise_std = sqrt(1/(2*rate*snr_lin)), rate=2, snr=10^0.7 ; double math to
    // match the float64->float32 cast in the reference.
    float nstd = (float)sqrt(1.0 / (4.0 * pow(10.0, 0.7)));
    v[t] = noise[t] * nstd;
    __syncthreads();
    float acc = 0.f;
#pragma unroll
    for (int j = 0; j < TAPS; j++) {
        int idx = t + 49 - j;   // 'same' mode: full[t + (TAPS-1)/2]
        if (idx >= 0 && idx < CUdim) acc = fmaf(fir[j], v[idx], acc);
    }
    nc_out[t] = acc;
    if (tail) tail[t] = acc;
}

// ---------------- stats -> affine (deterministic reduction) ---------------
__global__ void k_affine(const float* __restrict__ ps, const float* __restrict__ pq,
                         const float* __restrict__ g,  const float* __restrict__ bt,
                         float* __restrict__ alpha, float* __restrict__ beta)
{
    int j = blockIdx.x, t = threadIdx.x;   // 128 threads
    float s = 0.f, q = 0.f;
    for (int i = t; i < 512; i += 128) { s += ps[j*512 + i]; q += pq[j*512 + i]; }
    __shared__ float rs[128], rq[128];
    rs[t] = s; rq[t] = q; __syncthreads();
    for (int o = 64; o > 0; o >>= 1) {
        if (t < o) { rs[t] += rs[t+o]; rq[t] += rq[t+o]; }
        __syncthreads();
    }
    if (t == 0) {
        float mu  = rs[0] * (1.f/65536.f);
        float var = rq[0] * (1.f/65536.f) - mu*mu;
        float a = g[j] * rsqrtf(var + EPSf);
        alpha[j] = a; beta[j] = bt[j] - mu*a;
    }
}

// ---------------- weight / bias folding ------------------------------------
__global__ void k_fold_w(const float* __restrict__ W, const float* __restrict__ alpha,
                         float* __restrict__ Wf, int total, int kmask)
{
    for (int i = blockIdx.x*blockDim.x + threadIdx.x; i < total; i += gridDim.x*blockDim.x)
        Wf[i] = W[i] * alpha[i & kmask];
}

__global__ void k_fold_b(const float* __restrict__ W, const float* __restrict__ beta,
                         const float* __restrict__ b, float* __restrict__ bf, int K)
{
    int j = blockIdx.x, t = threadIdx.x;   // 128 threads
    float acc = 0.f;
    for (int k = t; k < K; k += 128) acc += beta[k] * W[(size_t)j*K + k];
    __shared__ float r[128];
    r[t] = acc; __syncthreads();
    for (int o = 64; o > 0; o >>= 1) { if (t < o) r[t] += r[t+o]; __syncthreads(); }
    if (t == 0) bf[j] = b[j] + r[0];
}

// ---------------- GEMM: C[M,N] = epi(A[M,K] @ W[N,K]^T + bias) -------------
// EPI 0: v = rowscale_i*acc + bias_j ; prelu ; store ; column sum/sq partials
// EPI 1: v = acc + bias_j ; store ; per-row  s_i = sqrt(CU / sum_j v^2)
// EPI 2: v = acc + bias_j ; store
template<int BM, int BN, int TM, int TN, int EPI>
__global__ void __launch_bounds__((BM/TM)*(BN/TN))
gemm_k(const float* __restrict__ A, const float* __restrict__ W,
       const float* __restrict__ bias, float* __restrict__ C,
       int K, int N,
       const float* __restrict__ rowscale, const float* __restrict__ slope_p,
       float* __restrict__ p1, float* __restrict__ p2)
{
    constexpr int NT = (BM/TM)*(BN/TN);
    constexpr int TX = BN/TN;
    constexpr int TY = BM/TM;

    __shared__ float As[16][BM];
    __shared__ float Ws[16][BN];

    const int tid = threadIdx.x;
    const int tx = tid % TX, ty = tid / TX;
    const int rowg0 = blockIdx.y * BM;
    const int colg0 = blockIdx.x * BN;

    float acc[TM][TN];
#pragma unroll
    for (int i = 0; i < TM; i++)
#pragma unroll
        for (int j = 0; j < TN; j++) acc[i][j] = 0.f;

    const int nkt = K >> 4;
    for (int kt = 0; kt < nkt; kt++) {
        __syncthreads();
#pragma unroll
        for (int i = tid; i < BM*4; i += NT) {
            int r = i >> 2, k4 = (i & 3) << 2;
            float4 v = *reinterpret_cast<const float4*>(A + (size_t)(rowg0+r)*K + (kt<<4) + k4);
            As[k4+0][r] = v.x; As[k4+1][r] = v.y; As[k4+2][r] = v.z; As[k4+3][r] = v.w;
        }
#pragma unroll
        for (int i = tid; i < BN*4; i += NT) {
            int r = i >> 2, k4 = (i & 3) << 2;
            float4 v = *reinterpret_cast<const float4*>(W + (size_t)(colg0+r)*K + (kt<<4) + k4);
            Ws[k4+0][r] = v.x; Ws[k4+1][r] = v.y; Ws[k4+2][r] = v.z; Ws[k4+3][r] = v.w;
        }
        __syncthreads();
#pragma unroll
        for (int kk = 0; kk < 16; kk++) {
            float a[TM], w[TN];
#pragma unroll
            for (int i = 0; i < TM; i++) a[i] = As[kk][ty*TM + i];
#pragma unroll
            for (int j = 0; j < TN; j++) w[j] = Ws[kk][tx*TN + j];
#pragma unroll
            for (int i = 0; i < TM; i++)
#pragma unroll
                for (int j = 0; j < TN; j++) acc[i][j] = fmaf(a[i], w[j], acc[i][j]);
        }
    }
    __syncthreads();   // allow shared reuse in epilogue

    float slope = 0.f;
    if (EPI == 0) slope = slope_p[0];

    // epilogue transform + store (mutate acc in place to save registers)
#pragma unroll
    for (int i = 0; i < TM; i++) {
        int row = rowg0 + ty*TM + i;
        float rsc = 1.f;
        if (EPI == 0) { if (rowscale) rsc = rowscale[row]; }
#pragma unroll
        for (int j = 0; j < TN; j++) {
            int col = colg0 + tx*TN + j;
            float v = acc[i][j];
            if (EPI == 0) v = v*rsc + bias[col];
            else          v = v + bias[col];
            if (EPI == 0) v = (v > 0.f) ? v : slope*v;
            acc[i][j] = v;
            C[(size_t)row*N + col] = v;
        }
    }

    if (EPI == 0) {
        // deterministic column partial sums for batch-norm stats
        float* red_s = &As[0][0];   // [TY][BN]
        float* red_q = &Ws[0][0];
#pragma unroll
        for (int j = 0; j < TN; j++) {
            float s = 0.f, q = 0.f;
#pragma unroll
            for (int i = 0; i < TM; i++) { float v = acc[i][j]; s += v; q += v*v; }
            red_s[ty*BN + tx*TN + j] = s;
            red_q[ty*BN + tx*TN + j] = q;
        }
        __syncthreads();
        if (tid < BN) {
            float s = 0.f, q = 0.f;
#pragma unroll
            for (int t = 0; t < TY; t++) { s += red_s[t*BN + tid]; q += red_q[t*BN + tid]; }
            p1[(size_t)(colg0 + tid)*gridDim.y + blockIdx.y] = s;
            p2[(size_t)(colg0 + tid)*gridDim.y + blockIdx.y] = q;
        }
    }
    if (EPI == 1) {
        // per-row L2 norm -> scale s_i = sqrt(CU)/||y_i||  (full N in one block)
        float* rr = &Ws[0][0];      // [BM][TX]
#pragma unroll
        for (int i = 0; i < TM; i++) {
            float q = 0.f;
#pragma unroll
            for (int j = 0; j < TN; j++) { float v = acc[i][j]; q += v*v; }
            rr[(ty*TM + i)*TX + tx] = q;
        }
        __syncthreads();
        if (tid < BM) {
            float q = 0.f;
#pragma unroll
            for (int t = 0; t < TX; t++) q += rr[tid*TX + t];
            p1[rowg0 + tid] = sqrtf((float)CUdim / q);
        }
    }
}

// ---------------- launch ----------------------------------------------------
extern "C" void kernel_launch(void* const* d_in, const int* in_sizes, int n_in,
                              void* d_out, int out_size)
{
    const float* x    = (const float*)d_in[0];
    const float* nois = (const float*)d_in[1];
    const float* W1   = (const float*)d_in[2];
    const float* b1   = (const float*)d_in[3];
    const float* a1   = (const float*)d_in[4];
    const float* g1   = (const float*)d_in[5];
    const float* bt1  = (const float*)d_in[6];
    const float* W2   = (const float*)d_in[7];
    const float* b2   = (const float*)d_in[8];
    const float* W3   = (const float*)d_in[9];
    const float* b3   = (const float*)d_in[10];
    const float* a2   = (const float*)d_in[11];
    const float* g2   = (const float*)d_in[12];
    const float* bt2  = (const float*)d_in[13];
    const float* W4   = (const float*)d_in[14];
    const float* b4   = (const float*)d_in[15];
    const float* fir  = (const float*)d_in[16];
    float* out = (float*)d_out;

    float* scr = nullptr;
    cudaGetSymbolAddress((void**)&scr, g_scratch);
    float* p_t   = scr + OFF_T;
    float* p_y   = scr + OFF_Y;
    float* p_d   = scr + OFF_D;
    float* p_s   = scr + OFF_S;
    float* p_ps  = scr + OFF_PS;
    float* p_pq  = scr + OFF_PQ;
    float* p_al  = scr + OFF_AL;
    float* p_be  = scr + OFF_BE;
    float* p_W2f = scr + OFF_W2F;
    float* p_b2f = scr + OFF_B2F;
    float* p_c3  = scr + OFF_C3;
    float* p_nc  = scr + OFF_NC;
    float* p_W4f = scr + OFF_W4F;
    float* p_b4f = scr + OFF_B4F;

    long long need = (long long)BSZ*BLK + CUdim;
    float* tail = ((long long)out_size >= need) ? out + (out_size - CUdim) : nullptr;

    // noise path (independent)
    k_noise<<<1, CUdim>>>(nois, fir, p_nc, tail);

    // stage 1: t = prelu(x@W1^T + b1) ; column stats
    gemm_k<128,128,8,8,0><<<dim3(BLK/128, BSZ/128), 256>>>(
        x, W1, b1, p_t, BLK, BLK, nullptr, a1, p_ps, p_pq);
    k_affine<<<BLK,128>>>(p_ps, p_pq, g1, bt1, p_al, p_be);
    k_fold_w<<<256,256>>>(W2, p_al, p_W2f, CUdim*BLK, BLK-1);
    k_fold_b<<<CUdim,128>>>(W2, p_be, b2, p_b2f, BLK);

    // stage 2: y = t@W2f^T + b2f ; s_i = sqrt(CU)/||y_i||
    gemm_k<128,256,8,8,1><<<dim3(1, BSZ/128), 512>>>(
        p_t, p_W2f, p_b2f, p_y, BLK, CUdim, nullptr, nullptr, p_s, nullptr);

    // c3_j = b3_j + nc . W3_j
    k_fold_b<<<BLK,128>>>(W3, p_nc, b3, p_c3, CUdim);

    // stage 3: d = prelu(s_i*(y@W3^T) + c3) ; column stats
    gemm_k<128,128,8,8,0><<<dim3(BLK/128, BSZ/128), 256>>>(
        p_y, W3, p_c3, p_d, CUdim, BLK, p_s, a2, p_ps, p_pq);
    k_affine<<<BLK,128>>>(p_ps, p_pq, g2, bt2, p_al, p_be);
    k_fold_w<<<512,256>>>(W4, p_al, p_W4f, BLK*BLK, BLK-1);
    k_fold_b<<<BLK,128>>>(W4, p_be, b4, p_b4f, BLK);

    // stage 4: out = d@W4f^T + b4f
    gemm_k<128,128,8,8,2><<<dim3(BLK/128, BSZ/128), 256>>>(
        p_d, p_W4f, p_b4f, out, BLK, BLK, nullptr, nullptr, nullptr, nullptr);
}

// round 2
// speedup vs baseline: 1.0025x; 1.0025x over previous
#include <cuda_runtime.h>
#include <math.h>

#define BSZ   65536
#define BLK   512
#define CUdim 256
#define TAPS  100
#define EPSf  1e-5f

// ---------------- scratch (one big device global; no allocations) ----------
// offsets in floats
#define OFF_T    0ull                          // t  [BSZ*BLK]
#define OFF_Y    (OFF_T  + (size_t)BSZ*BLK)    // y  [BSZ*CU]
#define OFF_D    (OFF_Y  + (size_t)BSZ*CUdim)  // d  [BSZ*BLK]
#define OFF_S    (OFF_D  + (size_t)BSZ*BLK)    // s  [BSZ]
#define OFF_PS   (OFF_S  + (size_t)BSZ)        // col-sum partials [BLK*512]
#define OFF_PQ   (OFF_PS + (size_t)BLK*512)    // col-sq  partials [BLK*512]
#define OFF_AL   (OFF_PQ + (size_t)BLK*512)    // alpha [BLK]
#define OFF_BE   (OFF_AL + BLK)                // beta  [BLK]
#define OFF_W2F  (OFF_BE + BLK)                // W2f [CU*BLK]
#define OFF_B2F  (OFF_W2F + (size_t)CUdim*BLK) // b2f [CU]
#define OFF_C3   (OFF_B2F + CUdim)             // c3  [BLK]
#define OFF_NC   (OFF_C3 + BLK)                // nc  [CU]
#define OFF_W4F  (OFF_NC + CUdim)              // W4f [BLK*BLK]
#define OFF_B4F  (OFF_W4F + (size_t)BLK*BLK)   // b4f [BLK]
#define SCRATCH_TOTAL (OFF_B4F + BLK)

__device__ float g_scratch[SCRATCH_TOTAL];

// ---------------- noise FIR kernel ----------------------------------------
__global__ void k_noise(const float* __restrict__ noise,
                        const float* __restrict__ fir,
                        float* __restrict__ nc_out,
                        float* __restrict__ tail)
{
    __shared__ float v[CUdim];
    int t = threadIdx.x;
    // noise_std = sqrt(1/(2*rate*snr_lin)), rate=2, snr=10^0.7 ; double math to
    // match the float64->float32 cast in the reference.
    float nstd = (float)sqrt(1.0 / (4.0 * pow(10.0, 0.7)));
    v[t] = noise[t] * nstd;
    __syncthreads();
    float acc = 0.f;
#pragma unroll
    for (int j = 0; j < TAPS; j++) {
        int idx = t + 49 - j;   // 'same' mode: full[t + (TAPS-1)/2]
        if (idx >= 0 && idx < CUdim) acc = fmaf(fir[j], v[idx], acc);
    }
    nc_out[t] = acc;
    if (tail) tail[t] = acc;
}

// ---------------- stats -> affine (deterministic reduction) ---------------
__global__ void k_affine(const float* __restrict__ ps, const float* __restrict__ pq,
                         const float* __restrict__ g,  const float* __restrict__ bt,
                         float* __restrict__ alpha, float* __restrict__ beta)
{
    int j = blockIdx.x, t = threadIdx.x;   // 128 threads
    float s = 0.f, q = 0.f;
    for (int i = t; i < 512; i += 128) { s += ps[j*512 + i]; q += pq[j*512 + i]; }
    __shared__ float rs[128], rq[128];
    rs[t] = s; rq[t] = q; __syncthreads();
    for (int o = 64; o > 0; o >>= 1) {
        if (t < o) { rs[t] += rs[t+o]; rq[t] += rq[t+o]; }
        __syncthreads();
    }
    if (t == 0) {
        float mu  = rs[0] * (1.f/65536.f);
        float var = rq[0] * (1.f/65536.f) - mu*mu;
        float a = g[j] * rsqrtf(var + EPSf);
        alpha[j] = a; beta[j] = bt[j] - mu*a;
    }
}

// ---------------- weight / bias folding ------------------------------------
__global__ void k_fold_w(const float* __restrict__ W, const float* __restrict__ alpha,
                         float* __restrict__ Wf, int total, int kmask)
{
    for (int i = blockIdx.x*blockDim.x + threadIdx.x; i < total; i += gridDim.x*blockDim.x)
        Wf[i] = W[i] * alpha[i & kmask];
}

__global__ void k_fold_b(const float* __restrict__ W, const float* __restrict__ beta,
                         const float* __restrict__ b, float* __restrict__ bf, int K)
{
    int j = blockIdx.x, t = threadIdx.x;   // 128 threads
    float acc = 0.f;
    for (int k = t; k < K; k += 128) acc += beta[k] * W[(size_t)j*K + k];
    __shared__ float r[128];
    r[t] = acc; __syncthreads();
    for (int o = 64; o > 0; o >>= 1) { if (t < o) r[t] += r[t+o]; __syncthreads(); }
    if (t == 0) bf[j] = b[j] + r[0];
}

// ---------------- GEMM: C[M,N] = epi(A[M,K] @ W[N,K]^T + bias) -------------
// EPI 0: v = rowscale_i*acc + bias_j ; prelu ; store ; column sum/sq partials
// EPI 1: v = acc + bias_j ; store ; per-row  s_i = sqrt(CU / sum_j v^2)
// EPI 2: v = acc + bias_j ; store
template<int BM, int BN, int TM, int TN, int EPI>
__global__ void __launch_bounds__((BM/TM)*(BN/TN))
gemm_k(const float* __restrict__ A, const float* __restrict__ W,
       const float* __restrict__ bias, float* __restrict__ C,
       int K, int N,
       const float* __restrict__ rowscale, const float* __restrict__ slope_p,
       float* __restrict__ p1, float* __restrict__ p2)
{
    constexpr int NT = (BM/TM)*(BN/TN);
    constexpr int TX = BN/TN;
    constexpr int TY = BM/TM;

    __shared__ float As[16][BM];
    __shared__ float Ws[16][BN];

    const int tid = threadIdx.x;
    const int tx = tid % TX, ty = tid / TX;
    const int rowg0 = blockIdx.y * BM;
    const int colg0 = blockIdx.x * BN;

    float acc[TM][TN];
#pragma unroll
    for (int i = 0; i < TM; i++)
#pragma unroll
        for (int j = 0; j < TN; j++) acc[i][j] = 0.f;

    const int nkt = K >> 4;
    for (int kt = 0; kt < nkt; kt++) {
        __syncthreads();
#pragma unroll
        for (int i = tid; i < BM*4; i += NT) {
            int r = i >> 2, k4 = (i & 3) << 2;
            float4 v = *reinterpret_cast<const float4*>(A + (size_t)(rowg0+r)*K + (kt<<4) + k4);
            As[k4+0][r] = v.x; As[k4+1][r] = v.y; As[k4+2][r] = v.z; As[k4+3][r] = v.w;
        }
#pragma unroll
        for (int i = tid; i < BN*4; i += NT) {
            int r = i >> 2, k4 = (i & 3) << 2;
            float4 v = *reinterpret_cast<const float4*>(W + (size_t)(colg0+r)*K + (kt<<4) + k4);
            Ws[k4+0][r] = v.x; Ws[k4+1][r] = v.y; Ws[k4+2][r] = v.z; Ws[k4+3][r] = v.w;
        }
        __syncthreads();
#pragma unroll
        for (int kk = 0; kk < 16; kk++) {
            float a[TM], w[TN];
#pragma unroll
            for (int i = 0; i < TM; i++) a[i] = As[kk][ty*TM + i];
#pragma unroll
            for (int j = 0; j < TN; j++) w[j] = Ws[kk][tx*TN + j];
#pragma unroll
            for (int i = 0; i < TM; i++)
#pragma unroll
                for (int j = 0; j < TN; j++) acc[i][j] = fmaf(a[i], w[j], acc[i][j]);
        }
    }
    __syncthreads();   // allow shared reuse in epilogue

    float slope = 0.f;
    if (EPI == 0) slope = slope_p[0];

    // epilogue transform + store (mutate acc in place to save registers)
#pragma unroll
    for (int i = 0; i < TM; i++) {
        int row = rowg0 + ty*TM + i;
        float rsc = 1.f;
        if (EPI == 0) { if (rowscale) rsc = rowscale[row]; }
#pragma unroll
        for (int j = 0; j < TN; j++) {
            int col = colg0 + tx*TN + j;
            float v = acc[i][j];
            if (EPI == 0) v = v*rsc + bias[col];
            else          v = v + bias[col];
            if (EPI == 0) v = (v > 0.f) ? v : slope*v;
            acc[i][j] = v;
            C[(size_t)row*N + col] = v;
        }
    }

    if (EPI == 0) {
        // deterministic column partial sums for batch-norm stats
        float* red_s = &As[0][0];   // [TY][BN]
        float* red_q = &Ws[0][0];
#pragma unroll
        for (int j = 0; j < TN; j++) {
            float s = 0.f, q = 0.f;
#pragma unroll
            for (int i = 0; i < TM; i++) { float v = acc[i][j]; s += v; q += v*v; }
            red_s[ty*BN + tx*TN + j] = s;
            red_q[ty*BN + tx*TN + j] = q;
        }
        __syncthreads();
        if (tid < BN) {
            float s = 0.f, q = 0.f;
#pragma unroll
            for (int t = 0; t < TY; t++) { s += red_s[t*BN + tid]; q += red_q[t*BN + tid]; }
            p1[(size_t)(colg0 + tid)*gridDim.y + blockIdx.y] = s;
            p2[(size_t)(colg0 + tid)*gridDim.y + blockIdx.y] = q;
        }
    }
    if (EPI == 1) {
        // per-row L2 norm -> scale s_i = sqrt(CU)/||y_i||  (full N in one block)
        float* rr = &Ws[0][0];      // [BM][TX]
#pragma unroll
        for (int i = 0; i < TM; i++) {
            float q = 0.f;
#pragma unroll
            for (int j = 0; j < TN; j++) { float v = acc[i][j]; q += v*v; }
            rr[(ty*TM + i)*TX + tx] = q;
        }
        __syncthreads();
        if (tid < BM) {
            float q = 0.f;
#pragma unroll
            for (int t = 0; t < TX; t++) q += rr[tid*TX + t];
            p1[rowg0 + tid] = sqrtf((float)CUdim / q);
        }
    }
}

// ---------------- launch ----------------------------------------------------
extern "C" void kernel_launch(void* const* d_in, const int* in_sizes, int n_in,
                              void* d_out, int out_size)
{
    const float* x    = (const float*)d_in[0];
    const float* nois = (const float*)d_in[1];
    const float* W1   = (const float*)d_in[2];
    const float* b1   = (const float*)d_in[3];
    const float* a1   = (const float*)d_in[4];
    const float* g1   = (const float*)d_in[5];
    const float* bt1  = (const float*)d_in[6];
    const float* W2   = (const float*)d_in[7];
    const float* b2   = (const float*)d_in[8];
    const float* W3   = (const float*)d_in[9];
    const float* b3   = (const float*)d_in[10];
    const float* a2   = (const float*)d_in[11];
    const float* g2   = (const float*)d_in[12];
    const float* bt2  = (const float*)d_in[13];
    const float* W4   = (const float*)d_in[14];
    const float* b4   = (const float*)d_in[15];
    const float* fir  = (const float*)d_in[16];
    float* out = (float*)d_out;

    float* scr = nullptr;
    cudaGetSymbolAddress((void**)&scr, g_scratch);
    float* p_t   = scr + OFF_T;
    float* p_y   = scr + OFF_Y;
    float* p_d   = scr + OFF_D;
    float* p_s   = scr + OFF_S;
    float* p_ps  = scr + OFF_PS;
    float* p_pq  = scr + OFF_PQ;
    float* p_al  = scr + OFF_AL;
    float* p_be  = scr + OFF_BE;
    float* p_W2f = scr + OFF_W2F;
    float* p_b2f = scr + OFF_B2F;
    float* p_c3  = scr + OFF_C3;
    float* p_nc  = scr + OFF_NC;
    float* p_W4f = scr + OFF_W4F;
    float* p_b4f = scr + OFF_B4F;

    long long need = (long long)BSZ*BLK + CUdim;
    float* tail = ((long long)out_size >= need) ? out + (out_size - CUdim) : nullptr;

    // noise path (independent)
    k_noise<<<1, CUdim>>>(nois, fir, p_nc, tail);

    // stage 1: t = prelu(x@W1^T + b1) ; column stats
    gemm_k<128,128,8,8,0><<<dim3(BLK/128, BSZ/128), 256>>>(
        x, W1, b1, p_t, BLK, BLK, nullptr, a1, p_ps, p_pq);
    k_affine<<<BLK,128>>>(p_ps, p_pq, g1, bt1, p_al, p_be);
    k_fold_w<<<256,256>>>(W2, p_al, p_W2f, CUdim*BLK, BLK-1);
    k_fold_b<<<CUdim,128>>>(W2, p_be, b2, p_b2f, BLK);

    // stage 2: y = t@W2f^T + b2f ; s_i = sqrt(CU)/||y_i||
    gemm_k<128,256,8,8,1><<<dim3(1, BSZ/128), 512>>>(
        p_t, p_W2f, p_b2f, p_y, BLK, CUdim, nullptr, nullptr, p_s, nullptr);

    // c3_j = b3_j + nc . W3_j
    k_fold_b<<<BLK,128>>>(W3, p_nc, b3, p_c3, CUdim);

    // stage 3: d = prelu(s_i*(y@W3^T) + c3) ; column stats
    gemm_k<128,128,8,8,0><<<dim3(BLK/128, BSZ/128), 256>>>(
        p_y, W3, p_c3, p_d, CUdim, BLK, p_s, a2, p_ps, p_pq);
    k_affine<<<BLK,128>>>(p_ps, p_pq, g2, bt2, p_al, p_be);
    k_fold_w<<<512,256>>>(W4, p_al, p_W4f, BLK*BLK, BLK-1);
    k_fold_b<<<BLK,128>>>(W4, p_be, b4, p_b4f, BLK);

    // stage 4: out = d@W4f^T + b4f
    gemm_k<128,128,8,8,2><<<dim3(BLK/128, BSZ/128), 256>>>(
        p_d, p_W4f, p_b4f, out, BLK, BLK, nullptr, nullptr, nullptr, nullptr);
}

// round 4
// speedup vs baseline: 2.2233x; 2.2178x over previous
#include <cuda_runtime.h>
#include <math.h>
#include <stdint.h>

#define BSZ  65536
#define EPSf 1e-5f

// ===================== scratch layout (4-byte units) ========================
#define U_XH  0ull                       // x/d hi plane [65536*512] halves
#define U_XL  (U_XH  + 16777216ull)
#define U_TH  (U_XL  + 16777216ull)
#define U_TL  (U_TH  + 16777216ull)
#define U_YH  (U_TL  + 16777216ull)      // y planes [65536*256] halves
#define U_YL  (U_YH  + 8388608ull)
#define U_S   (U_YL  + 8388608ull)       // 65536
#define U_PS  (U_S   + 65536ull)         // 512*128
#define U_PQ  (U_PS  + 65536ull)
#define U_AL  (U_PQ  + 65536ull)
#define U_BE  (U_AL  + 512ull)
#define U_W1H (U_BE  + 512ull)
#define U_W1L (U_W1H + 131072ull)
#define U_W2H (U_W1L + 131072ull)
#define U_W2L (U_W2H + 65536ull)
#define U_W3H (U_W2L + 65536ull)
#define U_W3L (U_W3H + 65536ull)
#define U_W4H (U_W3L + 65536ull)
#define U_W4L (U_W4H + 131072ull)
#define U_B2F (U_W4L + 131072ull)
#define U_C3  (U_B2F + 256ull)
#define U_NC  (U_C3  + 512ull)
#define U_B4F (U_NC  + 256ull)
#define U_TOT (U_B4F + 512ull)

__device__ __align__(1024) float g_scratch[U_TOT];

// ===================== helpers ==============================================
__device__ __forceinline__ uint32_t smem_u32(const void* p) {
    uint32_t a;
    asm("{ .reg .u64 t; cvta.to.shared.u64 t, %1; cvt.u32.u64 %0, t; }" : "=r"(a) : "l"(p));
    return a;
}
__device__ __forceinline__ void cpa16(uint32_t dst, const void* src) {
    asm volatile("cp.async.cg.shared.global [%0], [%1], 16;" :: "r"(dst), "l"(src) : "memory");
}
__device__ __forceinline__ void cpa_commit() {
    asm volatile("cp.async.commit_group;" ::: "memory");
}
template<int N> __device__ __forceinline__ void cpa_wait() {
    asm volatile("cp.async.wait_group %0;" :: "n"(N) : "memory");
}
__device__ __forceinline__ void mma_bf16(float* d, const uint32_t* a, uint32_t b0, uint32_t b1) {
    asm volatile("mma.sync.aligned.m16n8k16.row.col.f32.bf16.bf16.f32 "
        "{%0,%1,%2,%3}, {%4,%5,%6,%7}, {%8,%9}, {%0,%1,%2,%3};"
        : "+f"(d[0]), "+f"(d[1]), "+f"(d[2]), "+f"(d[3])
        : "r"(a[0]), "r"(a[1]), "r"(a[2]), "r"(a[3]), "r"(b0), "r"(b1));
}
__device__ __forceinline__ uint32_t cvt2bf(float hi, float lo) {
    uint32_t r;
    asm("cvt.rn.bf16x2.f32 %0, %1, %2;" : "=r"(r) : "f"(hi), "f"(lo));
    return r;
}

// ===================== small kernels ========================================
__global__ void k_noise(const float* __restrict__ noise, const float* __restrict__ fir,
                        float* __restrict__ nc_out, float* __restrict__ tail)
{
    __shared__ float v[256];
    int t = threadIdx.x;
    float nstd = (float)sqrt(1.0 / (4.0 * pow(10.0, 0.7)));
    v[t] = noise[t] * nstd;
    __syncthreads();
    float acc = 0.f;
#pragma unroll
    for (int j = 0; j < 100; j++) {
        int idx = t + 49 - j;
        if (idx >= 0 && idx < 256) acc = fmaf(fir[j], v[idx], acc);
    }
    nc_out[t] = acc;
    if (tail) tail[t] = acc;
}

// split fp32 -> (hi, lo) bf16 planes (pairs packed in u32); optional alpha fold
__global__ void k_split(const float* __restrict__ W, const float* __restrict__ alpha,
                        uint32_t* __restrict__ Ph, uint32_t* __restrict__ Pl,
                        int total_u32, int kmask)
{
    for (int i = blockIdx.x*blockDim.x + threadIdx.x; i < total_u32; i += gridDim.x*blockDim.x) {
        float v0 = W[2*i], v1 = W[2*i + 1];
        if (alpha) { v0 *= alpha[(2*i) & kmask]; v1 *= alpha[(2*i + 1) & kmask]; }
        uint32_t h = cvt2bf(v1, v0);
        float h0 = __uint_as_float(h << 16), h1 = __uint_as_float(h & 0xFFFF0000u);
        uint32_t l = cvt2bf(v1 - h1, v0 - h0);
        Ph[i] = h; Pl[i] = l;
    }
}

// column stats over hi/lo planes [65536 x 512] (u32 pitch 256), 128 chunks x 512 rows
__global__ void k_stats(const uint32_t* __restrict__ Ph, const uint32_t* __restrict__ Pl,
                        float* __restrict__ ps, float* __restrict__ pq)
{
    int chunk = blockIdx.x, t = threadIdx.x;  // 256 threads: u32 col t -> cols 2t, 2t+1
    float s0 = 0.f, q0 = 0.f, s1 = 0.f, q1 = 0.f;
    size_t base = (size_t)chunk * 512 * 256;
    for (int r = 0; r < 512; r++) {
        uint32_t h = Ph[base + (size_t)r*256 + t];
        uint32_t l = Pl[base + (size_t)r*256 + t];
        float v0 = __uint_as_float(h << 16) + __uint_as_float(l << 16);
        float v1 = __uint_as_float(h & 0xFFFF0000u) + __uint_as_float(l & 0xFFFF0000u);
        s0 += v0; q0 = fmaf(v0, v0, q0);
        s1 += v1; q1 = fmaf(v1, v1, q1);
    }
    ps[(size_t)(2*t)*128 + chunk] = s0;     pq[(size_t)(2*t)*128 + chunk] = q0;
    ps[(size_t)(2*t+1)*128 + chunk] = s1;   pq[(size_t)(2*t+1)*128 + chunk] = q1;
}

__global__ void k_affine(const float* __restrict__ ps, const float* __restrict__ pq,
                         const float* __restrict__ g, const float* __restrict__ bt,
                         float* __restrict__ alpha, float* __restrict__ beta)
{
    int j = blockIdx.x, t = threadIdx.x;   // 128 threads
    __shared__ float rs[128], rq[128];
    rs[t] = ps[j*128 + t]; rq[t] = pq[j*128 + t];
    __syncthreads();
    for (int o = 64; o > 0; o >>= 1) {
        if (t < o) { rs[t] += rs[t+o]; rq[t] += rq[t+o]; }
        __syncthreads();
    }
    if (t == 0) {
        float mu  = rs[0] * (1.f/65536.f);
        float var = rq[0] * (1.f/65536.f) - mu*mu;
        float a = g[j] * rsqrtf(var + EPSf);
        alpha[j] = a; beta[j] = bt[j] - mu*a;
    }
}

// per-row L2 scale over y planes [65536 x 256] (u32 pitch 128): s=sqrt(256/q)
__global__ void k_rownorm(const uint32_t* __restrict__ Ph, const uint32_t* __restrict__ Pl,
                          float* __restrict__ s)
{
    int w = threadIdx.x >> 5, lid = threadIdx.x & 31;
    int row = blockIdx.x * 4 + w;
    size_t base = (size_t)row * 128;
    float q = 0.f;
#pragma unroll
    for (int i = lid; i < 128; i += 32) {
        uint32_t h = Ph[base + i], l = Pl[base + i];
        float v0 = __uint_as_float(h << 16) + __uint_as_float(l << 16);
        float v1 = __uint_as_float(h & 0xFFFF0000u) + __uint_as_float(l & 0xFFFF0000u);
        q = fmaf(v0, v0, fmaf(v1, v1, q));
    }
#pragma unroll
    for (int o = 16; o > 0; o >>= 1) q += __shfl_xor_sync(0xFFFFFFFFu, q, o);
    if (lid == 0) s[row] = sqrtf(256.f / q);
}

__global__ void k_fold_b(const float* __restrict__ W, const float* __restrict__ beta,
                         const float* __restrict__ b, float* __restrict__ bf, int K)
{
    int j = blockIdx.x, t = threadIdx.x;   // 128 threads
    float acc = 0.f;
    for (int k = t; k < K; k += 128) acc += beta[k] * W[(size_t)j*K + k];
    __shared__ float r[128];
    r[t] = acc; __syncthreads();
    for (int o = 64; o > 0; o >>= 1) { if (t < o) r[t] += r[t+o]; __syncthreads(); }
    if (t == 0) bf[j] = b[j] + r[0];
}

// ===================== HMMA GEMM ============================================
// C[M,N] = epi( A[M,K] @ W[N,K]^T + bias )
// BM=128 BN=128 KC=64, 256 threads, 8 warps (4M x 2N), warp tile 32x64
// MODE 0: +bias, prelu, store planes
// MODE 1: +bias, store planes
// MODE 2: rowscale*acc + bias, prelu, store planes
// MODE 3: +bias, store fp32
#define PLB   18432              // plane bytes: 128 rows * 144B
#define BUFB  (4*PLB)
#define SMEMSZ (2*BUFB)
#define PIT32 36                 // smem row pitch in u32

template<int MODE>
__global__ void __launch_bounds__(256, 1)
gemm_hmma(const uint32_t* __restrict__ Ah, const uint32_t* __restrict__ Al,
          const uint32_t* __restrict__ Wh, const uint32_t* __restrict__ Wl,
          const float* __restrict__ bias,
          uint32_t* __restrict__ Ch, uint32_t* __restrict__ Cl, float* __restrict__ Cf,
          const float* __restrict__ rowscale, const float* __restrict__ slope_p,
          int K, int Ntot)
{
    extern __shared__ __align__(1024) char smem[];
    const uint32_t sb = smem_u32(smem);
    const int tid = threadIdx.x;
    const int wid = tid >> 5, lid = tid & 31;
    const int wm = wid & 3, wn = wid >> 2;
    const int g = lid >> 2, t = lid & 3;
    const int row0 = blockIdx.y * 128;
    const int col0 = blockIdx.x * 128;
    const int nkt = K >> 6;

    const char* srcs[4] = {(const char*)Ah, (const char*)Al, (const char*)Wh, (const char*)Wl};
    const int rb0[4] = {row0, row0, col0, col0};

    // ---- prefetch chunk 0 ----
    {
#pragma unroll
        for (int p = 0; p < 4; p++) {
            const char* sp = srcs[p];
            uint32_t dp = sb + p*PLB;
#pragma unroll
            for (int i = tid; i < 1024; i += 256) {
                int r = i >> 3, sg = i & 7;
                cpa16(dp + r*144 + sg*16, sp + ((size_t)(rb0[p] + r)*K)*2 + sg*16);
            }
        }
        cpa_commit();
    }

    float acc[2][8][4];
#pragma unroll
    for (int mt = 0; mt < 2; mt++)
#pragma unroll
        for (int nt = 0; nt < 8; nt++)
#pragma unroll
            for (int c = 0; c < 4; c++) acc[mt][nt][c] = 0.f;

    for (int kt = 0; kt < nkt; kt++) {
        const int b = kt & 1;
        if (kt + 1 < nkt) {
#pragma unroll
            for (int p = 0; p < 4; p++) {
                const char* sp = srcs[p];
                uint32_t dp = sb + (1 - b)*BUFB + p*PLB;
#pragma unroll
                for (int i = tid; i < 1024; i += 256) {
                    int r = i >> 3, sg = i & 7;
                    cpa16(dp + r*144 + sg*16,
                          sp + ((size_t)(rb0[p] + r)*K + (kt + 1)*64)*2 + sg*16);
                }
            }
            cpa_commit();
            cpa_wait<1>();
        } else {
            cpa_wait<0>();
        }
        __syncthreads();

        const uint32_t* pAh = (const uint32_t*)(smem + b*BUFB);
        const uint32_t* pAl = (const uint32_t*)(smem + b*BUFB + PLB);
        const uint32_t* pWh = (const uint32_t*)(smem + b*BUFB + 2*PLB);
        const uint32_t* pWl = (const uint32_t*)(smem + b*BUFB + 3*PLB);
        const int ra = (wm*32 + g)*PIT32;
        const int rbn = (wn*64 + g)*PIT32;

#pragma unroll
        for (int ks = 0; ks < 4; ks++) {
            const int ko = ks*8 + t;
            uint32_t ah[2][4], al[2][4];
#pragma unroll
            for (int mt = 0; mt < 2; mt++) {
                int base = ra + mt*(16*PIT32) + ko;
                ah[mt][0] = pAh[base];                ah[mt][1] = pAh[base + 8*PIT32];
                ah[mt][2] = pAh[base + 4];            ah[mt][3] = pAh[base + 8*PIT32 + 4];
                al[mt][0] = pAl[base];                al[mt][1] = pAl[base + 8*PIT32];
                al[mt][2] = pAl[base + 4];            al[mt][3] = pAl[base + 8*PIT32 + 4];
            }
#pragma unroll
            for (int nt = 0; nt < 8; nt++) {
                int bb = rbn + nt*(8*PIT32) + ko;
                uint32_t bh0 = pWh[bb], bh1 = pWh[bb + 4];
                uint32_t bl0 = pWl[bb], bl1 = pWl[bb + 4];
#pragma unroll
                for (int mt = 0; mt < 2; mt++) {
                    mma_bf16(acc[mt][nt], ah[mt], bh0, bh1);
                    mma_bf16(acc[mt][nt], ah[mt], bl0, bl1);
                    mma_bf16(acc[mt][nt], al[mt], bh0, bh1);
                }
            }
        }
        __syncthreads();
    }

    // ---- epilogue ----
    const float slope = (MODE == 0 || MODE == 2) ? slope_p[0] : 0.f;
    const int pitch_u32 = Ntot >> 1;
#pragma unroll
    for (int mt = 0; mt < 2; mt++) {
        const int r_lo = row0 + wm*32 + mt*16 + g;
        const int r_hi = r_lo + 8;
        float rs0 = 1.f, rs1 = 1.f;
        if (MODE == 2) { rs0 = rowscale[r_lo]; rs1 = rowscale[r_hi]; }
#pragma unroll
        for (int nt = 0; nt < 8; nt++) {
            const int c = col0 + wn*64 + nt*8 + t*2;
            const float b0 = bias[c], b1 = bias[c + 1];
            float v0 = acc[mt][nt][0], v1 = acc[mt][nt][1];
            float v2 = acc[mt][nt][2], v3 = acc[mt][nt][3];
            if (MODE == 2) {
                v0 = fmaf(v0, rs0, b0); v1 = fmaf(v1, rs0, b1);
                v2 = fmaf(v2, rs1, b0); v3 = fmaf(v3, rs1, b1);
            } else {
                v0 += b0; v1 += b1; v2 += b0; v3 += b1;
            }
            if (MODE == 0 || MODE == 2) {
                v0 = (v0 > 0.f) ? v0 : slope*v0;
                v1 = (v1 > 0.f) ? v1 : slope*v1;
                v2 = (v2 > 0.f) ? v2 : slope*v2;
                v3 = (v3 > 0.f) ? v3 : slope*v3;
            }
            if (MODE == 3) {
                *(float2*)&Cf[(size_t)r_lo*Ntot + c] = make_float2(v0, v1);
                *(float2*)&Cf[(size_t)r_hi*Ntot + c] = make_float2(v2, v3);
            } else {
                uint32_t h01 = cvt2bf(v1, v0);
                float h0 = __uint_as_float(h01 << 16), h1 = __uint_as_float(h01 & 0xFFFF0000u);
                uint32_t l01 = cvt2bf(v1 - h1, v0 - h0);
                uint32_t h23 = cvt2bf(v3, v2);
                float h2 = __uint_as_float(h23 << 16), h3 = __uint_as_float(h23 & 0xFFFF0000u);
                uint32_t l23 = cvt2bf(v3 - h3, v2 - h2);
                size_t i_lo = (size_t)r_lo*pitch_u32 + (c >> 1);
                size_t i_hi = (size_t)r_hi*pitch_u32 + (c >> 1);
                Ch[i_lo] = h01; Cl[i_lo] = l01;
                Ch[i_hi] = h23; Cl[i_hi] = l23;
            }
        }
    }
}

// ===================== launch ================================================
extern "C" void kernel_launch(void* const* d_in, const int* in_sizes, int n_in,
                              void* d_out, int out_size)
{
    const float* x    = (const float*)d_in[0];
    const float* nois = (const float*)d_in[1];
    const float* W1   = (const float*)d_in[2];
    const float* b1   = (const float*)d_in[3];
    const float* a1   = (const float*)d_in[4];
    const float* g1   = (const float*)d_in[5];
    const float* bt1  = (const float*)d_in[6];
    const float* W2   = (const float*)d_in[7];
    const float* b2   = (const float*)d_in[8];
    const float* W3   = (const float*)d_in[9];
    const float* b3   = (const float*)d_in[10];
    const float* a2   = (const float*)d_in[11];
    const float* g2   = (const float*)d_in[12];
    const float* bt2  = (const float*)d_in[13];
    const float* W4   = (const float*)d_in[14];
    const float* b4   = (const float*)d_in[15];
    const float* fir  = (const float*)d_in[16];
    float* out = (float*)d_out;

    float* scr = nullptr;
    cudaGetSymbolAddress((void**)&scr, g_scratch);
    uint32_t* XH = (uint32_t*)(scr + U_XH);  uint32_t* XL = (uint32_t*)(scr + U_XL);
    uint32_t* TH = (uint32_t*)(scr + U_TH);  uint32_t* TL = (uint32_t*)(scr + U_TL);
    uint32_t* YH = (uint32_t*)(scr + U_YH);  uint32_t* YL = (uint32_t*)(scr + U_YL);
    float* S  = scr + U_S;
    float* PS = scr + U_PS;  float* PQ = scr + U_PQ;
    float* AL = scr + U_AL;  float* BE = scr + U_BE;
    uint32_t* W1H = (uint32_t*)(scr + U_W1H); uint32_t* W1L = (uint32_t*)(scr + U_W1L);
    uint32_t* W2H = (uint32_t*)(scr + U_W2H); uint32_t* W2L = (uint32_t*)(scr + U_W2L);
    uint32_t* W3H = (uint32_t*)(scr + U_W3H); uint32_t* W3L = (uint32_t*)(scr + U_W3L);
    uint32_t* W4H = (uint32_t*)(scr + U_W4H); uint32_t* W4L = (uint32_t*)(scr + U_W4L);
    float* B2F = scr + U_B2F; float* C3 = scr + U_C3;
    float* NC  = scr + U_NC;  float* B4F = scr + U_B4F;

    cudaFuncSetAttribute(gemm_hmma<0>, cudaFuncAttributeMaxDynamicSharedMemorySize, SMEMSZ);
    cudaFuncSetAttribute(gemm_hmma<1>, cudaFuncAttributeMaxDynamicSharedMemorySize, SMEMSZ);
    cudaFuncSetAttribute(gemm_hmma<2>, cudaFuncAttributeMaxDynamicSharedMemorySize, SMEMSZ);
    cudaFuncSetAttribute(gemm_hmma<3>, cudaFuncAttributeMaxDynamicSharedMemorySize, SMEMSZ);

    long long need = (long long)BSZ*512 + 256;
    float* tail = ((long long)out_size >= need) ? out + (out_size - 256) : nullptr;

    // independent prep
    k_noise<<<1, 256>>>(nois, fir, NC, tail);
    k_split<<<4096, 256>>>(x,  nullptr, XH, XL, 16777216, 511);
    k_split<<<128, 256>>>(W1, nullptr, W1H, W1L, 131072, 511);
    k_split<<<64,  256>>>(W3, nullptr, W3H, W3L, 65536, 255);

    // stage 1: t = prelu(x@W1^T + b1)
    gemm_hmma<0><<<dim3(4, 512), 256, SMEMSZ>>>(
        XH, XL, W1H, W1L, b1, TH, TL, nullptr, nullptr, a1, 512, 512);
    k_stats<<<128, 256>>>(TH, TL, PS, PQ);
    k_affine<<<512, 128>>>(PS, PQ, g1, bt1, AL, BE);
    k_split<<<64, 256>>>(W2, AL, W2H, W2L, 65536, 511);
    k_fold_b<<<256, 128>>>(W2, BE, b2, B2F, 512);

    // stage 2: y = t_bn @ W2f^T + b2f
    gemm_hmma<1><<<dim3(2, 512), 256, SMEMSZ>>>(
        TH, TL, W2H, W2L, B2F, YH, YL, nullptr, nullptr, nullptr, 512, 256);
    k_rownorm<<<16384, 128>>>(YH, YL, S);
    k_fold_b<<<512, 128>>>(W3, NC, b3, C3, 256);

    // stage 3: d = prelu(s_i*(y@W3^T) + c3)   (d reuses x planes)
    gemm_hmma<2><<<dim3(4, 512), 256, SMEMSZ>>>(
        YH, YL, W3H, W3L, C3, XH, XL, nullptr, S, a2, 256, 512);
    k_stats<<<128, 256>>>(XH, XL, PS, PQ);
    k_affine<<<512, 128>>>(PS, PQ, g2, bt2, AL, BE);
    k_split<<<128, 256>>>(W4, AL, W4H, W4L, 131072, 511);
    k_fold_b<<<512, 128>>>(W4, BE, b4, B4F, 512);

    // stage 4: out = d_bn @ W4f^T + b4f (fp32)
    gemm_hmma<3><<<dim3(4, 512), 256, SMEMSZ>>>(
        XH, XL, W4H, W4L, B4F, nullptr, nullptr, out, nullptr, nullptr, 512, 512);
}

// round 5
// speedup vs baseline: 2.5499x; 1.1469x over previous
#include <cuda_runtime.h>
#include <math.h>
#include <stdint.h>

#define BSZ  65536
#define EPSf 1e-5f

// ===================== scratch layout (4-byte units) ========================
#define U_XH  0ull
#define U_XL  (U_XH  + 16777216ull)
#define U_TH  (U_XL  + 16777216ull)
#define U_TL  (U_TH  + 16777216ull)
#define U_YH  (U_TL  + 16777216ull)
#define U_YL  (U_YH  + 8388608ull)
#define U_S   (U_YL  + 8388608ull)
#define U_PS  (U_S   + 65536ull)
#define U_PQ  (U_PS  + 262144ull)
#define U_QP  (U_PQ  + 262144ull)
#define U_AL  (U_QP  + 131072ull)
#define U_BE  (U_AL  + 512ull)
#define U_W1H (U_BE  + 512ull)
#define U_W1L (U_W1H + 131072ull)
#define U_W2H (U_W1L + 131072ull)
#define U_W2L (U_W2H + 65536ull)
#define U_W3H (U_W2L + 65536ull)
#define U_W3L (U_W3H + 65536ull)
#define U_W4H (U_W3L + 65536ull)
#define U_W4L (U_W4H + 131072ull)
#define U_B2F (U_W4L + 131072ull)
#define U_C3  (U_B2F + 256ull)
#define U_NC  (U_C3  + 512ull)
#define U_B4F (U_NC  + 256ull)
#define U_TOT (U_B4F + 512ull)

__device__ __align__(1024) float g_scratch[U_TOT];

// ===================== helpers ==============================================
__device__ __forceinline__ uint32_t smem_u32(const void* p) {
    uint32_t a;
    asm("{ .reg .u64 t; cvta.to.shared.u64 t, %1; cvt.u32.u64 %0, t; }" : "=r"(a) : "l"(p));
    return a;
}
__device__ __forceinline__ void cpa16(uint32_t dst, const void* src) {
    asm volatile("cp.async.cg.shared.global [%0], [%1], 16;" :: "r"(dst), "l"(src) : "memory");
}
__device__ __forceinline__ void cpa_commit() {
    asm volatile("cp.async.commit_group;" ::: "memory");
}
template<int N> __device__ __forceinline__ void cpa_wait() {
    asm volatile("cp.async.wait_group %0;" :: "n"(N) : "memory");
}
__device__ __forceinline__ void ldsm4(uint32_t* r, uint32_t addr) {
    asm volatile("ldmatrix.sync.aligned.m8n8.x4.shared.b16 {%0,%1,%2,%3}, [%4];"
        : "=r"(r[0]), "=r"(r[1]), "=r"(r[2]), "=r"(r[3]) : "r"(addr));
}
__device__ __forceinline__ void mma_bf16(float* d, const uint32_t* a, uint32_t b0, uint32_t b1) {
    asm volatile("mma.sync.aligned.m16n8k16.row.col.f32.bf16.bf16.f32 "
        "{%0,%1,%2,%3}, {%4,%5,%6,%7}, {%8,%9}, {%0,%1,%2,%3};"
        : "+f"(d[0]), "+f"(d[1]), "+f"(d[2]), "+f"(d[3])
        : "r"(a[0]), "r"(a[1]), "r"(a[2]), "r"(a[3]), "r"(b0), "r"(b1));
}
__device__ __forceinline__ uint32_t cvt2bf(float hi, float lo) {
    uint32_t r;
    asm("cvt.rn.bf16x2.f32 %0, %1, %2;" : "=r"(r) : "f"(hi), "f"(lo));
    return r;
}

// ===================== small kernels ========================================
__global__ void k_noise(const float* __restrict__ noise, const float* __restrict__ fir,
                        float* __restrict__ nc_out, float* __restrict__ tail)
{
    __shared__ float v[256];
    int t = threadIdx.x;
    float nstd = (float)sqrt(1.0 / (4.0 * pow(10.0, 0.7)));
    v[t] = noise[t] * nstd;
    __syncthreads();
    float acc = 0.f;
#pragma unroll
    for (int j = 0; j < 100; j++) {
        int idx = t + 49 - j;
        if (idx >= 0 && idx < 256) acc = fmaf(fir[j], v[idx], acc);
    }
    nc_out[t] = acc;
    if (tail) tail[t] = acc;
}

// split fp32 -> (hi, lo) bf16 planes, float4-wide; optional alpha fold
__global__ void k_split4(const float4* __restrict__ W, const float* __restrict__ alpha,
                         uint2* __restrict__ Ph, uint2* __restrict__ Pl,
                         int total4, int kmask)
{
    for (int i = blockIdx.x*blockDim.x + threadIdx.x; i < total4; i += gridDim.x*blockDim.x) {
        float4 v = W[i];
        if (alpha) {
            int k = (4*i) & kmask;
            v.x *= alpha[k]; v.y *= alpha[k+1]; v.z *= alpha[k+2]; v.w *= alpha[k+3];
        }
        uint32_t h0 = cvt2bf(v.y, v.x), h1 = cvt2bf(v.w, v.z);
        float a0 = __uint_as_float(h0 << 16), a1 = __uint_as_float(h0 & 0xFFFF0000u);
        float a2 = __uint_as_float(h1 << 16), a3 = __uint_as_float(h1 & 0xFFFF0000u);
        uint32_t l0 = cvt2bf(v.y - a1, v.x - a0), l1 = cvt2bf(v.w - a3, v.z - a2);
        Ph[i] = make_uint2(h0, h1);
        Pl[i] = make_uint2(l0, l1);
    }
}

__global__ void k_affine(const float* __restrict__ ps, const float* __restrict__ pq,
                         const float* __restrict__ g, const float* __restrict__ bt,
                         float* __restrict__ alpha, float* __restrict__ beta)
{
    int j = blockIdx.x, t = threadIdx.x;   // 128 threads, 512 partials
    float s = 0.f, q = 0.f;
    for (int i = t; i < 512; i += 128) { s += ps[j*512 + i]; q += pq[j*512 + i]; }
    __shared__ float rs[128], rq[128];
    rs[t] = s; rq[t] = q; __syncthreads();
    for (int o = 64; o > 0; o >>= 1) {
        if (t < o) { rs[t] += rs[t+o]; rq[t] += rq[t+o]; }
        __syncthreads();
    }
    if (t == 0) {
        float mu  = rs[0] * (1.f/65536.f);
        float var = rq[0] * (1.f/65536.f) - mu*mu;
        float a = g[j] * rsqrtf(var + EPSf);
        alpha[j] = a; beta[j] = bt[j] - mu*a;
    }
}

__global__ void k_scale(const float* __restrict__ qp, float* __restrict__ s)
{
    int r = blockIdx.x*256 + threadIdx.x;
    s[r] = sqrtf(256.f / (qp[r] + qp[65536 + r]));
}

__global__ void k_fold_b(const float* __restrict__ W, const float* __restrict__ beta,
                         const float* __restrict__ b, float* __restrict__ bf, int K)
{
    int j = blockIdx.x, t = threadIdx.x;
    float acc = 0.f;
    for (int k = t; k < K; k += 128) acc += beta[k] * W[(size_t)j*K + k];
    __shared__ float r[128];
    r[t] = acc; __syncthreads();
    for (int o = 64; o > 0; o >>= 1) { if (t < o) r[t] += r[t+o]; __syncthreads(); }
    if (t == 0) bf[j] = b[j] + r[0];
}

// ===================== HMMA GEMM ============================================
// C[M,N] = epi( A[M,K] @ W[N,K]^T + bias )
// BM=128 BN=128 KC=64, 256 threads, 8 warps (4M x 2N), warp tile 32x64
// MODE 0: +bias, prelu, store planes, col stats partials
// MODE 1: +bias, store planes, row sumsq partials
// MODE 2: rowscale*acc + bias, prelu, store planes, col stats partials
// MODE 3: +bias, store fp32
#define PLB    18432
#define BUFB   (4*PLB)
#define SMEMSZ (2*BUFB)

template<int MODE>
__global__ void __launch_bounds__(256, 1)
gemm_hmma(const uint32_t* __restrict__ Ah, const uint32_t* __restrict__ Al,
          const uint32_t* __restrict__ Wh, const uint32_t* __restrict__ Wl,
          const float* __restrict__ bias,
          uint32_t* __restrict__ Ch, uint32_t* __restrict__ Cl, float* __restrict__ Cf,
          const float* __restrict__ rowscale, const float* __restrict__ slope_p,
          float* __restrict__ ps, float* __restrict__ pq, float* __restrict__ qp,
          int K, int Ntot)
{
    extern __shared__ __align__(1024) char smem[];
    __shared__ float bias_s[128];
    const uint32_t sb = smem_u32(smem);
    const int tid = threadIdx.x;
    const int wid = tid >> 5, lid = tid & 31;
    const int wm = wid & 3, wn = wid >> 2;
    const int g = lid >> 2, t = lid & 3;
    const int row0 = blockIdx.y * 128;
    const int col0 = blockIdx.x * 128;
    const int nkt = K >> 6;

    if (tid < 128) bias_s[tid] = bias[col0 + tid];

    const char* srcs[4] = {(const char*)Ah, (const char*)Al, (const char*)Wh, (const char*)Wl};
    const int rb0[4] = {row0, row0, col0, col0};

    // prefetch chunk 0
#pragma unroll
    for (int p = 0; p < 4; p++) {
        const char* sp = srcs[p];
        uint32_t dp = sb + p*PLB;
#pragma unroll
        for (int i = tid; i < 1024; i += 256) {
            int r = i >> 3, sg = i & 7;
            cpa16(dp + r*144 + sg*16, sp + ((size_t)(rb0[p] + r)*K)*2 + sg*16);
        }
    }
    cpa_commit();

    // ldmatrix lane addressing
    const int lr  = lid & 7;
    const int lb3 = (lid >> 3) & 1;
    const int lb4 = (lid >> 4) & 1;
    uint32_t a_off[2], b_off[4];
#pragma unroll
    for (int mt = 0; mt < 2; mt++)
        a_off[mt] = (uint32_t)((wm*32 + mt*16 + lb3*8 + lr)*144 + lb4*16);
#pragma unroll
    for (int j = 0; j < 4; j++)
        b_off[j] = (uint32_t)((wn*64 + j*16 + lb4*8 + lr)*144 + lb3*16);

    float acc[2][8][4];
#pragma unroll
    for (int mt = 0; mt < 2; mt++)
#pragma unroll
        for (int nt = 0; nt < 8; nt++)
#pragma unroll
            for (int c = 0; c < 4; c++) acc[mt][nt][c] = 0.f;

    for (int kt = 0; kt < nkt; kt++) {
        const int b = kt & 1;
        if (kt + 1 < nkt) {
#pragma unroll
            for (int p = 0; p < 4; p++) {
                const char* sp = srcs[p];
                uint32_t dp = sb + (1 - b)*BUFB + p*PLB;
#pragma unroll
                for (int i = tid; i < 1024; i += 256) {
                    int r = i >> 3, sg = i & 7;
                    cpa16(dp + r*144 + sg*16,
                          sp + ((size_t)(rb0[p] + r)*K + (kt + 1)*64)*2 + sg*16);
                }
            }
            cpa_commit();
            cpa_wait<1>();
        } else {
            cpa_wait<0>();
        }
        __syncthreads();

        const uint32_t sA = sb + b*BUFB;
        const uint32_t sW = sA + 2*PLB;

#pragma unroll
        for (int ks = 0; ks < 4; ks++) {
            uint32_t ah[2][4], al[2][4], bh[4][4], bl[4][4];
#pragma unroll
            for (int mt = 0; mt < 2; mt++) {
                ldsm4(ah[mt], sA + a_off[mt] + ks*32);
                ldsm4(al[mt], sA + PLB + a_off[mt] + ks*32);
            }
#pragma unroll
            for (int j = 0; j < 4; j++) {
                ldsm4(bh[j], sW + b_off[j] + ks*32);
                ldsm4(bl[j], sW + PLB + b_off[j] + ks*32);
            }
            // term-major: hi*hi, hi*lo, lo*hi — each acc touched once per 16 MMAs
#pragma unroll
            for (int j = 0; j < 4; j++)
#pragma unroll
                for (int jj = 0; jj < 2; jj++)
#pragma unroll
                    for (int mt = 0; mt < 2; mt++)
                        mma_bf16(acc[mt][j*2+jj], ah[mt], bh[j][jj*2], bh[j][jj*2+1]);
#pragma unroll
            for (int j = 0; j < 4; j++)
#pragma unroll
                for (int jj = 0; jj < 2; jj++)
#pragma unroll
                    for (int mt = 0; mt < 2; mt++)
                        mma_bf16(acc[mt][j*2+jj], ah[mt], bl[j][jj*2], bl[j][jj*2+1]);
#pragma unroll
            for (int j = 0; j < 4; j++)
#pragma unroll
                for (int jj = 0; jj < 2; jj++)
#pragma unroll
                    for (int mt = 0; mt < 2; mt++)
                        mma_bf16(acc[mt][j*2+jj], al[mt], bh[j][jj*2], bh[j][jj*2+1]);
        }
        __syncthreads();
    }

    // ---------------- epilogue --------------------------------------------
    const float slope = (MODE == 0 || MODE == 2) ? slope_p[0] : 0.f;
    float rsl[2][2];
    if (MODE == 2) {
#pragma unroll
        for (int mt = 0; mt < 2; mt++) {
            rsl[mt][0] = rowscale[row0 + wm*32 + mt*16 + g];
            rsl[mt][1] = rowscale[row0 + wm*32 + mt*16 + g + 8];
        }
    }
    float* col_s  = (float*)smem;        // [4][128]
    float* col_q  = col_s + 512;         // [4][128]
    float* rowred = col_q + 512;         // [2][128]
    float rq[4] = {0.f, 0.f, 0.f, 0.f};
    const int pitch_u32 = Ntot >> 1;
    const int t2 = t*2;

#pragma unroll
    for (int nt = 0; nt < 8; nt++) {
        const int cl = wn*64 + nt*8 + t2;
        const int c  = col0 + cl;
        const float b0 = bias_s[cl], b1 = bias_s[cl + 1];
        float cse = 0.f, cso = 0.f, cqe = 0.f, cqo = 0.f;
#pragma unroll
        for (int mt = 0; mt < 2; mt++) {
            const int r_lo = row0 + wm*32 + mt*16 + g;
            const int r_hi = r_lo + 8;
            float v0 = acc[mt][nt][0], v1 = acc[mt][nt][1];
            float v2 = acc[mt][nt][2], v3 = acc[mt][nt][3];
            if (MODE == 2) {
                v0 = fmaf(v0, rsl[mt][0], b0); v1 = fmaf(v1, rsl[mt][0], b1);
                v2 = fmaf(v2, rsl[mt][1], b0); v3 = fmaf(v3, rsl[mt][1], b1);
            } else {
                v0 += b0; v1 += b1; v2 += b0; v3 += b1;
            }
            if (MODE == 0 || MODE == 2) {
                v0 = (v0 > 0.f) ? v0 : slope*v0;
                v1 = (v1 > 0.f) ? v1 : slope*v1;
                v2 = (v2 > 0.f) ? v2 : slope*v2;
                v3 = (v3 > 0.f) ? v3 : slope*v3;
                cse += v0 + v2; cso += v1 + v3;
                cqe += v0*v0 + v2*v2; cqo += v1*v1 + v3*v3;
            }
            if (MODE == 1) {
                rq[mt*2]   += v0*v0 + v1*v1;
                rq[mt*2+1] += v2*v2 + v3*v3;
            }
            if (MODE == 3) {
                *(float2*)&Cf[(size_t)r_lo*Ntot + c] = make_float2(v0, v1);
                *(float2*)&Cf[(size_t)r_hi*Ntot + c] = make_float2(v2, v3);
            } else {
                uint32_t h01 = cvt2bf(v1, v0);
                float h0 = __uint_as_float(h01 << 16), h1 = __uint_as_float(h01 & 0xFFFF0000u);
                uint32_t l01 = cvt2bf(v1 - h1, v0 - h0);
                uint32_t h23 = cvt2bf(v3, v2);
                float h2 = __uint_as_float(h23 << 16), h3 = __uint_as_float(h23 & 0xFFFF0000u);
                uint32_t l23 = cvt2bf(v3 - h3, v2 - h2);
                size_t i_lo = (size_t)r_lo*pitch_u32 + (c >> 1);
                size_t i_hi = (size_t)r_hi*pitch_u32 + (c >> 1);
                Ch[i_lo] = h01; Cl[i_lo] = l01;
                Ch[i_hi] = h23; Cl[i_hi] = l23;
            }
        }
        if (MODE == 0 || MODE == 2) {
#pragma unroll
            for (int o = 4; o <= 16; o <<= 1) {
                cse += __shfl_xor_sync(0xFFFFFFFFu, cse, o);
                cso += __shfl_xor_sync(0xFFFFFFFFu, cso, o);
                cqe += __shfl_xor_sync(0xFFFFFFFFu, cqe, o);
                cqo += __shfl_xor_sync(0xFFFFFFFFu, cqo, o);
            }
            if (lid < 4) {
                col_s[wm*128 + cl]     = cse;
                col_s[wm*128 + cl + 1] = cso;
                col_q[wm*128 + cl]     = cqe;
                col_q[wm*128 + cl + 1] = cqo;
            }
        }
    }
    if (MODE == 1) {
#pragma unroll
        for (int i = 0; i < 4; i++) {
            rq[i] += __shfl_xor_sync(0xFFFFFFFFu, rq[i], 1);
            rq[i] += __shfl_xor_sync(0xFFFFFFFFu, rq[i], 2);
        }
        if (t == 0) {
            rowred[wn*128 + wm*32 + g]      = rq[0];
            rowred[wn*128 + wm*32 + g + 8]  = rq[1];
            rowred[wn*128 + wm*32 + g + 16] = rq[2];
            rowred[wn*128 + wm*32 + g + 24] = rq[3];
        }
    }
    if (MODE == 0 || MODE == 1 || MODE == 2) {
        __syncthreads();
        if ((MODE == 0 || MODE == 2) && tid < 128) {
            float s = col_s[tid] + col_s[128 + tid] + col_s[256 + tid] + col_s[384 + tid];
            float q = col_q[tid] + col_q[128 + tid] + col_q[256 + tid] + col_q[384 + tid];
            ps[(size_t)(col0 + tid)*gridDim.y + blockIdx.y] = s;
            pq[(size_t)(col0 + tid)*gridDim.y + blockIdx.y] = q;
        }
        if (MODE == 1 && tid < 128)
            qp[(size_t)blockIdx.x*65536 + row0 + tid] = rowred[tid] + rowred[128 + tid];
    }
}

// ===================== launch ================================================
extern "C" void kernel_launch(void* const* d_in, const int* in_sizes, int n_in,
                              void* d_out, int out_size)
{
    const float* x    = (const float*)d_in[0];
    const float* nois = (const float*)d_in[1];
    const float* W1   = (const float*)d_in[2];
    const float* b1   = (const float*)d_in[3];
    const float* a1   = (const float*)d_in[4];
    const float* g1   = (const float*)d_in[5];
    const float* bt1  = (const float*)d_in[6];
    const float* W2   = (const float*)d_in[7];
    const float* b2   = (const float*)d_in[8];
    const float* W3   = (const float*)d_in[9];
    const float* b3   = (const float*)d_in[10];
    const float* a2   = (const float*)d_in[11];
    const float* g2   = (const float*)d_in[12];
    const float* bt2  = (const float*)d_in[13];
    const float* W4   = (const float*)d_in[14];
    const float* b4   = (const float*)d_in[15];
    const float* fir  = (const float*)d_in[16];
    float* out = (float*)d_out;

    float* scr = nullptr;
    cudaGetSymbolAddress((void**)&scr, g_scratch);
    uint32_t* XH = (uint32_t*)(scr + U_XH);  uint32_t* XL = (uint32_t*)(scr + U_XL);
    uint32_t* TH = (uint32_t*)(scr + U_TH);  uint32_t* TL = (uint32_t*)(scr + U_TL);
    uint32_t* YH = (uint32_t*)(scr + U_YH);  uint32_t* YL = (uint32_t*)(scr + U_YL);
    float* S  = scr + U_S;
    float* PS = scr + U_PS;  float* PQ = scr + U_PQ;  float* QP = scr + U_QP;
    float* AL = scr + U_AL;  float* BE = scr + U_BE;
    uint32_t* W1H = (uint32_t*)(scr + U_W1H); uint32_t* W1L = (uint32_t*)(scr + U_W1L);
    uint32_t* W2H = (uint32_t*)(scr + U_W2H); uint32_t* W2L = (uint32_t*)(scr + U_W2L);
    uint32_t* W3H = (uint32_t*)(scr + U_W3H); uint32_t* W3L = (uint32_t*)(scr + U_W3L);
    uint32_t* W4H = (uint32_t*)(scr + U_W4H); uint32_t* W4L = (uint32_t*)(scr + U_W4L);
    float* B2F = scr + U_B2F; float* C3 = scr + U_C3;
    float* NC  = scr + U_NC;  float* B4F = scr + U_B4F;

    cudaFuncSetAttribute(gemm_hmma<0>, cudaFuncAttributeMaxDynamicSharedMemorySize, SMEMSZ);
    cudaFuncSetAttribute(gemm_hmma<1>, cudaFuncAttributeMaxDynamicSharedMemorySize, SMEMSZ);
    cudaFuncSetAttribute(gemm_hmma<2>, cudaFuncAttributeMaxDynamicSharedMemorySize, SMEMSZ);
    cudaFuncSetAttribute(gemm_hmma<3>, cudaFuncAttributeMaxDynamicSharedMemorySize, SMEMSZ);

    long long need = (long long)BSZ*512 + 256;
    float* tail = ((long long)out_size >= need) ? out + (out_size - 256) : nullptr;

    // independent prep
    k_noise<<<1, 256>>>(nois, fir, NC, tail);
    k_split4<<<2048, 256>>>((const float4*)x,  nullptr, (uint2*)XH, (uint2*)XL, 8388608, 511);
    k_split4<<<64, 256>>>((const float4*)W1, nullptr, (uint2*)W1H, (uint2*)W1L, 65536, 511);
    k_split4<<<32, 256>>>((const float4*)W3, nullptr, (uint2*)W3H, (uint2*)W3L, 32768, 255);

    // stage 1: t = prelu(x@W1^T + b1) ; col stats in epilogue
    gemm_hmma<0><<<dim3(4, 512), 256, SMEMSZ>>>(
        XH, XL, W1H, W1L, b1, TH, TL, nullptr, nullptr, a1, PS, PQ, nullptr, 512, 512);
    k_affine<<<512, 128>>>(PS, PQ, g1, bt1, AL, BE);
    k_split4<<<32, 256>>>((const float4*)W2, AL, (uint2*)W2H, (uint2*)W2L, 32768, 511);
    k_fold_b<<<256, 128>>>(W2, BE, b2, B2F, 512);

    // stage 2: y = t_bn @ W2f^T + b2f ; row sumsq partials
    gemm_hmma<1><<<dim3(2, 512), 256, SMEMSZ>>>(
        TH, TL, W2H, W2L, B2F, YH, YL, nullptr, nullptr, nullptr, nullptr, nullptr, QP, 512, 256);
    k_scale<<<256, 256>>>(QP, S);
    k_fold_b<<<512, 128>>>(W3, NC, b3, C3, 256);

    // stage 3: d = prelu(s_i*(y@W3^T) + c3) ; col stats (d reuses x planes)
    gemm_hmma<2><<<dim3(4, 512), 256, SMEMSZ>>>(
        YH, YL, W3H, W3L, C3, XH, XL, nullptr, S, a2, PS, PQ, nullptr, 256, 512);
    k_affine<<<512, 128>>>(PS, PQ, g2, bt2, AL, BE);
    k_split4<<<64, 256>>>((const float4*)W4, AL, (uint2*)W4H, (uint2*)W4L, 65536, 511);
    k_fold_b<<<512, 128>>>(W4, BE, b4, B4F, 512);

    // stage 4: out = d_bn @ W4f^T + b4f (fp32)
    gemm_hmma<3><<<dim3(4, 512), 256, SMEMSZ>>>(
        XH, XL, W4H, W4L, B4F, nullptr, nullptr, out, nullptr, nullptr,
        nullptr, nullptr, nullptr, 512, 512);
}

// round 6
// speedup vs baseline: 2.5512x; 1.0005x over previous
#include <cuda_runtime.h>
#include <math.h>
#include <stdint.h>

#define BSZ  65536
#define EPSf 1e-5f

// ===================== scratch layout (4-byte units) ========================
#define U_XH  0ull
#define U_XL  (U_XH  + 16777216ull)
#define U_TH  (U_XL  + 16777216ull)
#define U_TL  (U_TH  + 16777216ull)
#define U_YH  (U_TL  + 16777216ull)
#define U_YL  (U_YH  + 8388608ull)
#define U_S   (U_YL  + 8388608ull)
#define U_PS  (U_S   + 65536ull)
#define U_PQ  (U_PS  + 262144ull)
#define U_QP  (U_PQ  + 262144ull)
#define U_AL  (U_QP  + 131072ull)
#define U_BE  (U_AL  + 512ull)
#define U_W1H (U_BE  + 512ull)
#define U_W1L (U_W1H + 131072ull)
#define U_W2H (U_W1L + 131072ull)
#define U_W2L (U_W2H + 65536ull)
#define U_W3H (U_W2L + 65536ull)
#define U_W3L (U_W3H + 65536ull)
#define U_W4H (U_W3L + 65536ull)
#define U_W4L (U_W4H + 131072ull)
#define U_B2F (U_W4L + 131072ull)
#define U_C3  (U_B2F + 256ull)
#define U_NC  (U_C3  + 512ull)
#define U_B4F (U_NC  + 256ull)
#define U_TOT (U_B4F + 512ull)

__device__ __align__(1024) float g_scratch[U_TOT];

// ===================== helpers ==============================================
__device__ __forceinline__ uint32_t smem_u32(const void* p) {
    uint32_t a;
    asm("{ .reg .u64 t; cvta.to.shared.u64 t, %1; cvt.u32.u64 %0, t; }" : "=r"(a) : "l"(p));
    return a;
}
__device__ __forceinline__ void cpa16(uint32_t dst, const void* src) {
    asm volatile("cp.async.cg.shared.global [%0], [%1], 16;" :: "r"(dst), "l"(src) : "memory");
}
__device__ __forceinline__ void cpa_commit() {
    asm volatile("cp.async.commit_group;" ::: "memory");
}
template<int N> __device__ __forceinline__ void cpa_wait() {
    asm volatile("cp.async.wait_group %0;" :: "n"(N) : "memory");
}
__device__ __forceinline__ void ldsm4(uint32_t* r, uint32_t addr) {
    asm volatile("ldmatrix.sync.aligned.m8n8.x4.shared.b16 {%0,%1,%2,%3}, [%4];"
        : "=r"(r[0]), "=r"(r[1]), "=r"(r[2]), "=r"(r[3]) : "r"(addr));
}
__device__ __forceinline__ void mma_bf16(float* d, const uint32_t* a, uint32_t b0, uint32_t b1) {
    asm volatile("mma.sync.aligned.m16n8k16.row.col.f32.bf16.bf16.f32 "
        "{%0,%1,%2,%3}, {%4,%5,%6,%7}, {%8,%9}, {%0,%1,%2,%3};"
        : "+f"(d[0]), "+f"(d[1]), "+f"(d[2]), "+f"(d[3])
        : "r"(a[0]), "r"(a[1]), "r"(a[2]), "r"(a[3]), "r"(b0), "r"(b1));
}
__device__ __forceinline__ uint32_t cvt2bf(float hi, float lo) {
    uint32_t r;
    asm("cvt.rn.bf16x2.f32 %0, %1, %2;" : "=r"(r) : "f"(hi), "f"(lo));
    return r;
}

// ===================== small kernels ========================================
__global__ void k_noise(const float* __restrict__ noise, const float* __restrict__ fir,
                        float* __restrict__ nc_out, float* __restrict__ tail)
{
    __shared__ float v[256];
    int t = threadIdx.x;
    float nstd = (float)sqrt(1.0 / (4.0 * pow(10.0, 0.7)));
    v[t] = noise[t] * nstd;
    __syncthreads();
    float acc = 0.f;
#pragma unroll
    for (int j = 0; j < 100; j++) {
        int idx = t + 49 - j;
        if (idx >= 0 && idx < 256) acc = fmaf(fir[j], v[idx], acc);
    }
    nc_out[t] = acc;
    if (tail) tail[t] = acc;
}

// split fp32 -> (hi, lo) bf16 planes, float4-wide; optional alpha fold
__global__ void k_split4(const float4* __restrict__ W, const float* __restrict__ alpha,
                         uint2* __restrict__ Ph, uint2* __restrict__ Pl,
                         int total4, int kmask)
{
    for (int i = blockIdx.x*blockDim.x + threadIdx.x; i < total4; i += gridDim.x*blockDim.x) {
        float4 v = W[i];
        if (alpha) {
            int k = (4*i) & kmask;
            v.x *= alpha[k]; v.y *= alpha[k+1]; v.z *= alpha[k+2]; v.w *= alpha[k+3];
        }
        uint32_t h0 = cvt2bf(v.y, v.x), h1 = cvt2bf(v.w, v.z);
        float a0 = __uint_as_float(h0 << 16), a1 = __uint_as_float(h0 & 0xFFFF0000u);
        float a2 = __uint_as_float(h1 << 16), a3 = __uint_as_float(h1 & 0xFFFF0000u);
        uint32_t l0 = cvt2bf(v.y - a1, v.x - a0), l1 = cvt2bf(v.w - a3, v.z - a2);
        Ph[i] = make_uint2(h0, h1);
        Pl[i] = make_uint2(l0, l1);
    }
}

__global__ void k_affine(const float* __restrict__ ps, const float* __restrict__ pq,
                         const float* __restrict__ g, const float* __restrict__ bt,
                         float* __restrict__ alpha, float* __restrict__ beta)
{
    int j = blockIdx.x, t = threadIdx.x;   // 128 threads, 512 partials
    float s = 0.f, q = 0.f;
    for (int i = t; i < 512; i += 128) { s += ps[j*512 + i]; q += pq[j*512 + i]; }
    __shared__ float rs[128], rq[128];
    rs[t] = s; rq[t] = q; __syncthreads();
    for (int o = 64; o > 0; o >>= 1) {
        if (t < o) { rs[t] += rs[t+o]; rq[t] += rq[t+o]; }
        __syncthreads();
    }
    if (t == 0) {
        float mu  = rs[0] * (1.f/65536.f);
        float var = rq[0] * (1.f/65536.f) - mu*mu;
        float a = g[j] * rsqrtf(var + EPSf);
        alpha[j] = a; beta[j] = bt[j] - mu*a;
    }
}

__global__ void k_scale(const float* __restrict__ qp, float* __restrict__ s)
{
    int r = blockIdx.x*256 + threadIdx.x;
    s[r] = sqrtf(256.f / (qp[r] + qp[65536 + r]));
}

__global__ void k_fold_b(const float* __restrict__ W, const float* __restrict__ beta,
                         const float* __restrict__ b, float* __restrict__ bf, int K)
{
    int j = blockIdx.x, t = threadIdx.x;
    float acc = 0.f;
    for (int k = t; k < K; k += 128) acc += beta[k] * W[(size_t)j*K + k];
    __shared__ float r[128];
    r[t] = acc; __syncthreads();
    for (int o = 64; o > 0; o >>= 1) { if (t < o) r[t] += r[t+o]; __syncthreads(); }
    if (t == 0) bf[j] = b[j] + r[0];
}

// ===================== HMMA GEMM ============================================
// C[M,N] = epi( A[M,K] @ W[N,K]^T + bias )
// BM=128 BN=128 KC=64, 256 threads, 8 warps (4M x 2N), warp tile 32x64
// MODE 0: +bias, prelu, store planes, col stats partials
// MODE 1: +bias, store planes, row sumsq partials
// MODE 2: rowscale*acc + bias, prelu, store planes, col stats partials
// MODE 3: +bias, store fp32
#define PLB    18432
#define BUFB   (4*PLB)
#define SMEMSZ (2*BUFB)

template<int MODE>
__global__ void __launch_bounds__(256, 1)
gemm_hmma(const uint32_t* __restrict__ Ah, const uint32_t* __restrict__ Al,
          const uint32_t* __restrict__ Wh, const uint32_t* __restrict__ Wl,
          const float* __restrict__ bias,
          uint32_t* __restrict__ Ch, uint32_t* __restrict__ Cl, float* __restrict__ Cf,
          const float* __restrict__ rowscale, const float* __restrict__ slope_p,
          float* __restrict__ ps, float* __restrict__ pq, float* __restrict__ qp,
          int K, int Ntot)
{
    extern __shared__ __align__(1024) char smem[];
    __shared__ float bias_s[128];
    const uint32_t sb = smem_u32(smem);
    const int tid = threadIdx.x;
    const int wid = tid >> 5, lid = tid & 31;
    const int wm = wid & 3, wn = wid >> 2;
    const int g = lid >> 2, t = lid & 3;
    const int row0 = blockIdx.y * 128;
    const int col0 = blockIdx.x * 128;
    const int nkt = K >> 6;

    if (tid < 128) bias_s[tid] = bias[col0 + tid];

    const char* srcs[4] = {(const char*)Ah, (const char*)Al, (const char*)Wh, (const char*)Wl};
    const int rb0[4] = {row0, row0, col0, col0};

    // prefetch chunk 0
#pragma unroll
    for (int p = 0; p < 4; p++) {
        const char* sp = srcs[p];
        uint32_t dp = sb + p*PLB;
#pragma unroll
        for (int i = tid; i < 1024; i += 256) {
            int r = i >> 3, sg = i & 7;
            cpa16(dp + r*144 + sg*16, sp + ((size_t)(rb0[p] + r)*K)*2 + sg*16);
        }
    }
    cpa_commit();

    // ldmatrix lane addressing
    const int lr  = lid & 7;
    const int lb3 = (lid >> 3) & 1;
    const int lb4 = (lid >> 4) & 1;
    uint32_t a_off[2], b_off[4];
#pragma unroll
    for (int mt = 0; mt < 2; mt++)
        a_off[mt] = (uint32_t)((wm*32 + mt*16 + lb3*8 + lr)*144 + lb4*16);
#pragma unroll
    for (int j = 0; j < 4; j++)
        b_off[j] = (uint32_t)((wn*64 + j*16 + lb4*8 + lr)*144 + lb3*16);

    float acc[2][8][4];
#pragma unroll
    for (int mt = 0; mt < 2; mt++)
#pragma unroll
        for (int nt = 0; nt < 8; nt++)
#pragma unroll
            for (int c = 0; c < 4; c++) acc[mt][nt][c] = 0.f;

    for (int kt = 0; kt < nkt; kt++) {
        const int b = kt & 1;
        if (kt + 1 < nkt) {
#pragma unroll
            for (int p = 0; p < 4; p++) {
                const char* sp = srcs[p];
                uint32_t dp = sb + (1 - b)*BUFB + p*PLB;
#pragma unroll
                for (int i = tid; i < 1024; i += 256) {
                    int r = i >> 3, sg = i & 7;
                    cpa16(dp + r*144 + sg*16,
                          sp + ((size_t)(rb0[p] + r)*K + (kt + 1)*64)*2 + sg*16);
                }
            }
            cpa_commit();
            cpa_wait<1>();
        } else {
            cpa_wait<0>();
        }
        __syncthreads();

        const uint32_t sA = sb + b*BUFB;
        const uint32_t sW = sA + 2*PLB;

#pragma unroll
        for (int ks = 0; ks < 4; ks++) {
            uint32_t ah[2][4], al[2][4], bh[4][4], bl[4][4];
#pragma unroll
            for (int mt = 0; mt < 2; mt++) {
                ldsm4(ah[mt], sA + a_off[mt] + ks*32);
                ldsm4(al[mt], sA + PLB + a_off[mt] + ks*32);
            }
#pragma unroll
            for (int j = 0; j < 4; j++) {
                ldsm4(bh[j], sW + b_off[j] + ks*32);
                ldsm4(bl[j], sW + PLB + b_off[j] + ks*32);
            }
            // term-major: hi*hi, hi*lo, lo*hi — each acc touched once per 16 MMAs
#pragma unroll
            for (int j = 0; j < 4; j++)
#pragma unroll
                for (int jj = 0; jj < 2; jj++)
#pragma unroll
                    for (int mt = 0; mt < 2; mt++)
                        mma_bf16(acc[mt][j*2+jj], ah[mt], bh[j][jj*2], bh[j][jj*2+1]);
#pragma unroll
            for (int j = 0; j < 4; j++)
#pragma unroll
                for (int jj = 0; jj < 2; jj++)
#pragma unroll
                    for (int mt = 0; mt < 2; mt++)
                        mma_bf16(acc[mt][j*2+jj], ah[mt], bl[j][jj*2], bl[j][jj*2+1]);
#pragma unroll
            for (int j = 0; j < 4; j++)
#pragma unroll
                for (int jj = 0; jj < 2; jj++)
#pragma unroll
                    for (int mt = 0; mt < 2; mt++)
                        mma_bf16(acc[mt][j*2+jj], al[mt], bh[j][jj*2], bh[j][jj*2+1]);
        }
        __syncthreads();
    }

    // ---------------- epilogue --------------------------------------------
    const float slope = (MODE == 0 || MODE == 2) ? slope_p[0] : 0.f;
    float rsl[2][2];
    if (MODE == 2) {
#pragma unroll
        for (int mt = 0; mt < 2; mt++) {
            rsl[mt][0] = rowscale[row0 + wm*32 + mt*16 + g];
            rsl[mt][1] = rowscale[row0 + wm*32 + mt*16 + g + 8];
        }
    }
    float* col_s  = (float*)smem;        // [4][128]
    float* col_q  = col_s + 512;         // [4][128]
    float* rowred = col_q + 512;         // [2][128]
    float rq[4] = {0.f, 0.f, 0.f, 0.f};
    const int pitch_u32 = Ntot >> 1;
    const int t2 = t*2;

#pragma unroll
    for (int nt = 0; nt < 8; nt++) {
        const int cl = wn*64 + nt*8 + t2;
        const int c  = col0 + cl;
        const float b0 = bias_s[cl], b1 = bias_s[cl + 1];
        float cse = 0.f, cso = 0.f, cqe = 0.f, cqo = 0.f;
#pragma unroll
        for (int mt = 0; mt < 2; mt++) {
            const int r_lo = row0 + wm*32 + mt*16 + g;
            const int r_hi = r_lo + 8;
            float v0 = acc[mt][nt][0], v1 = acc[mt][nt][1];
            float v2 = acc[mt][nt][2], v3 = acc[mt][nt][3];
            if (MODE == 2) {
                v0 = fmaf(v0, rsl[mt][0], b0); v1 = fmaf(v1, rsl[mt][0], b1);
                v2 = fmaf(v2, rsl[mt][1], b0); v3 = fmaf(v3, rsl[mt][1], b1);
            } else {
                v0 += b0; v1 += b1; v2 += b0; v3 += b1;
            }
            if (MODE == 0 || MODE == 2) {
                v0 = (v0 > 0.f) ? v0 : slope*v0;
                v1 = (v1 > 0.f) ? v1 : slope*v1;
                v2 = (v2 > 0.f) ? v2 : slope*v2;
                v3 = (v3 > 0.f) ? v3 : slope*v3;
                cse += v0 + v2; cso += v1 + v3;
                cqe += v0*v0 + v2*v2; cqo += v1*v1 + v3*v3;
            }
            if (MODE == 1) {
                rq[mt*2]   += v0*v0 + v1*v1;
                rq[mt*2+1] += v2*v2 + v3*v3;
            }
            if (MODE == 3) {
                *(float2*)&Cf[(size_t)r_lo*Ntot + c] = make_float2(v0, v1);
                *(float2*)&Cf[(size_t)r_hi*Ntot + c] = make_float2(v2, v3);
            } else {
                uint32_t h01 = cvt2bf(v1, v0);
                float h0 = __uint_as_float(h01 << 16), h1 = __uint_as_float(h01 & 0xFFFF0000u);
                uint32_t l01 = cvt2bf(v1 - h1, v0 - h0);
                uint32_t h23 = cvt2bf(v3, v2);
                float h2 = __uint_as_float(h23 << 16), h3 = __uint_as_float(h23 & 0xFFFF0000u);
                uint32_t l23 = cvt2bf(v3 - h3, v2 - h2);
                size_t i_lo = (size_t)r_lo*pitch_u32 + (c >> 1);
                size_t i_hi = (size_t)r_hi*pitch_u32 + (c >> 1);
                Ch[i_lo] = h01; Cl[i_lo] = l01;
                Ch[i_hi] = h23; Cl[i_hi] = l23;
            }
        }
        if (MODE == 0 || MODE == 2) {
#pragma unroll
            for (int o = 4; o <= 16; o <<= 1) {
                cse += __shfl_xor_sync(0xFFFFFFFFu, cse, o);
                cso += __shfl_xor_sync(0xFFFFFFFFu, cso, o);
                cqe += __shfl_xor_sync(0xFFFFFFFFu, cqe, o);
                cqo += __shfl_xor_sync(0xFFFFFFFFu, cqo, o);
            }
            if (lid < 4) {
                col_s[wm*128 + cl]     = cse;
                col_s[wm*128 + cl + 1] = cso;
                col_q[wm*128 + cl]     = cqe;
                col_q[wm*128 + cl + 1] = cqo;
            }
        }
    }
    if (MODE == 1) {
#pragma unroll
        for (int i = 0; i < 4; i++) {
            rq[i] += __shfl_xor_sync(0xFFFFFFFFu, rq[i], 1);
            rq[i] += __shfl_xor_sync(0xFFFFFFFFu, rq[i], 2);
        }
        if (t == 0) {
            rowred[wn*128 + wm*32 + g]      = rq[0];
            rowred[wn*128 + wm*32 + g + 8]  = rq[1];
            rowred[wn*128 + wm*32 + g + 16] = rq[2];
            rowred[wn*128 + wm*32 + g + 24] = rq[3];
        }
    }
    if (MODE == 0 || MODE == 1 || MODE == 2) {
        __syncthreads();
        if ((MODE == 0 || MODE == 2) && tid < 128) {
            float s = col_s[tid] + col_s[128 + tid] + col_s[256 + tid] + col_s[384 + tid];
            float q = col_q[tid] + col_q[128 + tid] + col_q[256 + tid] + col_q[384 + tid];
            ps[(size_t)(col0 + tid)*gridDim.y + blockIdx.y] = s;
            pq[(size_t)(col0 + tid)*gridDim.y + blockIdx.y] = q;
        }
        if (MODE == 1 && tid < 128)
            qp[(size_t)blockIdx.x*65536 + row0 + tid] = rowred[tid] + rowred[128 + tid];
    }
}

// ===================== launch ================================================
extern "C" void kernel_launch(void* const* d_in, const int* in_sizes, int n_in,
                              void* d_out, int out_size)
{
    const float* x    = (const float*)d_in[0];
    const float* nois = (const float*)d_in[1];
    const float* W1   = (const float*)d_in[2];
    const float* b1   = (const float*)d_in[3];
    const float* a1   = (const float*)d_in[4];
    const float* g1   = (const float*)d_in[5];
    const float* bt1  = (const float*)d_in[6];
    const float* W2   = (const float*)d_in[7];
    const float* b2   = (const float*)d_in[8];
    const float* W3   = (const float*)d_in[9];
    const float* b3   = (const float*)d_in[10];
    const float* a2   = (const float*)d_in[11];
    const float* g2   = (const float*)d_in[12];
    const float* bt2  = (const float*)d_in[13];
    const float* W4   = (const float*)d_in[14];
    const float* b4   = (const float*)d_in[15];
    const float* fir  = (const float*)d_in[16];
    float* out = (float*)d_out;

    float* scr = nullptr;
    cudaGetSymbolAddress((void**)&scr, g_scratch);
    uint32_t* XH = (uint32_t*)(scr + U_XH);  uint32_t* XL = (uint32_t*)(scr + U_XL);
    uint32_t* TH = (uint32_t*)(scr + U_TH);  uint32_t* TL = (uint32_t*)(scr + U_TL);
    uint32_t* YH = (uint32_t*)(scr + U_YH);  uint32_t* YL = (uint32_t*)(scr + U_YL);
    float* S  = scr + U_S;
    float* PS = scr + U_PS;  float* PQ = scr + U_PQ;  float* QP = scr + U_QP;
    float* AL = scr + U_AL;  float* BE = scr + U_BE;
    uint32_t* W1H = (uint32_t*)(scr + U_W1H); uint32_t* W1L = (uint32_t*)(scr + U_W1L);
    uint32_t* W2H = (uint32_t*)(scr + U_W2H); uint32_t* W2L = (uint32_t*)(scr + U_W2L);
    uint32_t* W3H = (uint32_t*)(scr + U_W3H); uint32_t* W3L = (uint32_t*)(scr + U_W3L);
    uint32_t* W4H = (uint32_t*)(scr + U_W4H); uint32_t* W4L = (uint32_t*)(scr + U_W4L);
    float* B2F = scr + U_B2F; float* C3 = scr + U_C3;
    float* NC  = scr + U_NC;  float* B4F = scr + U_B4F;

    cudaFuncSetAttribute(gemm_hmma<0>, cudaFuncAttributeMaxDynamicSharedMemorySize, SMEMSZ);
    cudaFuncSetAttribute(gemm_hmma<1>, cudaFuncAttributeMaxDynamicSharedMemorySize, SMEMSZ);
    cudaFuncSetAttribute(gemm_hmma<2>, cudaFuncAttributeMaxDynamicSharedMemorySize, SMEMSZ);
    cudaFuncSetAttribute(gemm_hmma<3>, cudaFuncAttributeMaxDynamicSharedMemorySize, SMEMSZ);

    long long need = (long long)BSZ*512 + 256;
    float* tail = ((long long)out_size >= need) ? out + (out_size - 256) : nullptr;

    // independent prep
    k_noise<<<1, 256>>>(nois, fir, NC, tail);
    k_split4<<<2048, 256>>>((const float4*)x,  nullptr, (uint2*)XH, (uint2*)XL, 8388608, 511);
    k_split4<<<64, 256>>>((const float4*)W1, nullptr, (uint2*)W1H, (uint2*)W1L, 65536, 511);
    k_split4<<<32, 256>>>((const float4*)W3, nullptr, (uint2*)W3H, (uint2*)W3L, 32768, 255);

    // stage 1: t = prelu(x@W1^T + b1) ; col stats in epilogue
    gemm_hmma<0><<<dim3(4, 512), 256, SMEMSZ>>>(
        XH, XL, W1H, W1L, b1, TH, TL, nullptr, nullptr, a1, PS, PQ, nullptr, 512, 512);
    k_affine<<<512, 128>>>(PS, PQ, g1, bt1, AL, BE);
    k_split4<<<32, 256>>>((const float4*)W2, AL, (uint2*)W2H, (uint2*)W2L, 32768, 511);
    k_fold_b<<<256, 128>>>(W2, BE, b2, B2F, 512);

    // stage 2: y = t_bn @ W2f^T + b2f ; row sumsq partials
    gemm_hmma<1><<<dim3(2, 512), 256, SMEMSZ>>>(
        TH, TL, W2H, W2L, B2F, YH, YL, nullptr, nullptr, nullptr, nullptr, nullptr, QP, 512, 256);
    k_scale<<<256, 256>>>(QP, S);
    k_fold_b<<<512, 128>>>(W3, NC, b3, C3, 256);

    // stage 3: d = prelu(s_i*(y@W3^T) + c3) ; col stats (d reuses x planes)
    gemm_hmma<2><<<dim3(4, 512), 256, SMEMSZ>>>(
        YH, YL, W3H, W3L, C3, XH, XL, nullptr, S, a2, PS, PQ, nullptr, 256, 512);
    k_affine<<<512, 128>>>(PS, PQ, g2, bt2, AL, BE);
    k_split4<<<64, 256>>>((const float4*)W4, AL, (uint2*)W4H, (uint2*)W4L, 65536, 511);
    k_fold_b<<<512, 128>>>(W4, BE, b4, B4F, 512);

    // stage 4: out = d_bn @ W4f^T + b4f (fp32)
    gemm_hmma<3><<<dim3(4, 512), 256, SMEMSZ>>>(
        XH, XL, W4H, W4L, B4F, nullptr, nullptr, out, nullptr, nullptr,
        nullptr, nullptr, nullptr, 512, 512);
}

// round 7
// speedup vs baseline: 2.6163x; 1.0255x over previous
#include <cuda_runtime.h>
#include <math.h>
#include <stdint.h>

#define BSZ  65536
#define EPSf 1e-5f

// ===================== scratch layout (4-byte units) ========================
#define U_XH  0ull
#define U_XL  (U_XH  + 16777216ull)
#define U_TH  (U_XL  + 16777216ull)
#define U_TL  (U_TH  + 16777216ull)
#define U_YH  (U_TL  + 16777216ull)
#define U_YL  (U_YH  + 8388608ull)
#define U_S   (U_YL  + 8388608ull)
#define U_PS  (U_S   + 65536ull)
#define U_PQ  (U_PS  + 262144ull)
#define U_QP  (U_PQ  + 262144ull)
#define U_AL  (U_QP  + 131072ull)
#define U_BE  (U_AL  + 512ull)
#define U_W1H (U_BE  + 512ull)
#define U_W1L (U_W1H + 131072ull)
#define U_W2H (U_W1L + 131072ull)
#define U_W2L (U_W2H + 65536ull)
#define U_W3H (U_W2L + 65536ull)
#define U_W3L (U_W3H + 65536ull)
#define U_W4H (U_W3L + 65536ull)
#define U_W4L (U_W4H + 131072ull)
#define U_B2F (U_W4L + 131072ull)
#define U_C3  (U_B2F + 256ull)
#define U_NC  (U_C3  + 512ull)
#define U_B4F (U_NC  + 256ull)
#define U_TOT (U_B4F + 512ull)

__device__ __align__(1024) float g_scratch[U_TOT];

// ===================== helpers ==============================================
__device__ __forceinline__ uint32_t smem_u32(const void* p) {
    uint32_t a;
    asm("{ .reg .u64 t; cvta.to.shared.u64 t, %1; cvt.u32.u64 %0, t; }" : "=r"(a) : "l"(p));
    return a;
}
__device__ __forceinline__ void cpa16(uint32_t dst, const void* src) {
    asm volatile("cp.async.cg.shared.global [%0], [%1], 16;" :: "r"(dst), "l"(src) : "memory");
}
__device__ __forceinline__ void cpa_commit() {
    asm volatile("cp.async.commit_group;" ::: "memory");
}
template<int N> __device__ __forceinline__ void cpa_wait() {
    asm volatile("cp.async.wait_group %0;" :: "n"(N) : "memory");
}
__device__ __forceinline__ void ldsm4(uint32_t* r, uint32_t addr) {
    asm volatile("ldmatrix.sync.aligned.m8n8.x4.shared.b16 {%0,%1,%2,%3}, [%4];"
        : "=r"(r[0]), "=r"(r[1]), "=r"(r[2]), "=r"(r[3]) : "r"(addr));
}
__device__ __forceinline__ void mma_bf16(float* d, const uint32_t* a, uint32_t b0, uint32_t b1) {
    asm volatile("mma.sync.aligned.m16n8k16.row.col.f32.bf16.bf16.f32 "
        "{%0,%1,%2,%3}, {%4,%5,%6,%7}, {%8,%9}, {%0,%1,%2,%3};"
        : "+f"(d[0]), "+f"(d[1]), "+f"(d[2]), "+f"(d[3])
        : "r"(a[0]), "r"(a[1]), "r"(a[2]), "r"(a[3]), "r"(b0), "r"(b1));
}
__device__ __forceinline__ uint32_t cvt2bf(float hi, float lo) {
    uint32_t r;
    asm("cvt.rn.bf16x2.f32 %0, %1, %2;" : "=r"(r) : "f"(hi), "f"(lo));
    return r;
}

// ===================== small kernels ========================================
__global__ void k_noise(const float* __restrict__ noise, const float* __restrict__ fir,
                        float* __restrict__ nc_out, float* __restrict__ tail)
{
    __shared__ float v[256];
    int t = threadIdx.x;
    float nstd = (float)sqrt(1.0 / (4.0 * pow(10.0, 0.7)));
    v[t] = noise[t] * nstd;
    __syncthreads();
    float acc = 0.f;
#pragma unroll
    for (int j = 0; j < 100; j++) {
        int idx = t + 49 - j;
        if (idx >= 0 && idx < 256) acc = fmaf(fir[j], v[idx], acc);
    }
    nc_out[t] = acc;
    if (tail) tail[t] = acc;
}

__global__ void k_split4(const float4* __restrict__ W, const float* __restrict__ alpha,
                         uint2* __restrict__ Ph, uint2* __restrict__ Pl,
                         int total4, int kmask)
{
    for (int i = blockIdx.x*blockDim.x + threadIdx.x; i < total4; i += gridDim.x*blockDim.x) {
        float4 v = W[i];
        if (alpha) {
            int k = (4*i) & kmask;
            v.x *= alpha[k]; v.y *= alpha[k+1]; v.z *= alpha[k+2]; v.w *= alpha[k+3];
        }
        uint32_t h0 = cvt2bf(v.y, v.x), h1 = cvt2bf(v.w, v.z);
        float a0 = __uint_as_float(h0 << 16), a1 = __uint_as_float(h0 & 0xFFFF0000u);
        float a2 = __uint_as_float(h1 << 16), a3 = __uint_as_float(h1 & 0xFFFF0000u);
        uint32_t l0 = cvt2bf(v.y - a1, v.x - a0), l1 = cvt2bf(v.w - a3, v.z - a2);
        Ph[i] = make_uint2(h0, h1);
        Pl[i] = make_uint2(l0, l1);
    }
}

__global__ void k_affine(const float* __restrict__ ps, const float* __restrict__ pq,
                         const float* __restrict__ g, const float* __restrict__ bt,
                         float* __restrict__ alpha, float* __restrict__ beta, int np)
{
    int j = blockIdx.x, t = threadIdx.x;   // 128 threads
    float s = 0.f, q = 0.f;
    for (int i = t; i < np; i += 128) { s += ps[j*np + i]; q += pq[j*np + i]; }
    __shared__ float rs[128], rq[128];
    rs[t] = s; rq[t] = q; __syncthreads();
    for (int o = 64; o > 0; o >>= 1) {
        if (t < o) { rs[t] += rs[t+o]; rq[t] += rq[t+o]; }
        __syncthreads();
    }
    if (t == 0) {
        float mu  = rs[0] * (1.f/65536.f);
        float var = rq[0] * (1.f/65536.f) - mu*mu;
        float a = g[j] * rsqrtf(var + EPSf);
        alpha[j] = a; beta[j] = bt[j] - mu*a;
    }
}

__global__ void k_scale(const float* __restrict__ qp, float* __restrict__ s)
{
    int r = blockIdx.x*256 + threadIdx.x;
    s[r] = sqrtf(256.f / (qp[r] + qp[65536 + r]));
}

__global__ void k_fold_b(const float* __restrict__ W, const float* __restrict__ beta,
                         const float* __restrict__ b, float* __restrict__ bf, int K)
{
    int j = blockIdx.x, t = threadIdx.x;
    float acc = 0.f;
    for (int k = t; k < K; k += 128) acc += beta[k] * W[(size_t)j*K + k];
    __shared__ float r[128];
    r[t] = acc; __syncthreads();
    for (int o = 64; o > 0; o >>= 1) { if (t < o) r[t] += r[t+o]; __syncthreads(); }
    if (t == 0) bf[j] = b[j] + r[0];
}

// ===================== HMMA GEMM ============================================
// C[M,N] = epi( A[M,K] @ W[N,K]^T + bias )
// BM=256 BN=128 KC=64, 256 threads, 8 warps (4M x 2N), warp tile 64x64
// MODE 0: +bias, prelu, store planes, col stats partials
// MODE 1: +bias, store planes, row sumsq partials
// MODE 2: rowscale*acc + bias, prelu, store planes, col stats partials
// MODE 3: +bias, store fp32
#define APLB   36864            // A plane bytes: 256 rows * 144
#define WPLB   18432            // W plane bytes: 128 rows * 144
#define BUFB   (2*APLB + 2*WPLB)
#define SMEMSZ (2*BUFB)

template<int MODE>
__global__ void __launch_bounds__(256, 1)
gemm_hmma(const uint32_t* __restrict__ Ah, const uint32_t* __restrict__ Al,
          const uint32_t* __restrict__ Wh, const uint32_t* __restrict__ Wl,
          const float* __restrict__ bias,
          uint32_t* __restrict__ Ch, uint32_t* __restrict__ Cl, float* __restrict__ Cf,
          const float* __restrict__ rowscale, const float* __restrict__ slope_p,
          float* __restrict__ ps, float* __restrict__ pq, float* __restrict__ qp,
          int K, int Ntot)
{
    extern __shared__ __align__(1024) char smem[];
    __shared__ float bias_s[128];
    const uint32_t sb = smem_u32(smem);
    const int tid = threadIdx.x;
    const int wid = tid >> 5, lid = tid & 31;
    const int wm = wid & 3, wn = wid >> 2;
    const int g = lid >> 2, t = lid & 3;
    const int row0 = blockIdx.y * 256;
    const int col0 = blockIdx.x * 128;
    const int nkt = K >> 6;

    if (tid < 128) bias_s[tid] = bias[col0 + tid];

    // chunk loader: 6144 cp.async of 16B
    const char* cAh = (const char*)Ah;  const char* cAl = (const char*)Al;
    const char* cWh = (const char*)Wh;  const char* cWl = (const char*)Wl;

#define LOAD_CHUNK(BUF, KT)                                                       \
    do {                                                                          \
        uint32_t dbase = sb + (BUF)*BUFB;                                         \
        size_t koff = (size_t)(KT)*64*2;                                          \
        _Pragma("unroll")                                                         \
        for (int i = tid; i < 4096; i += 256) {                                   \
            int pl = i >> 11, r = (i >> 3) & 255, sg = i & 7;                     \
            const char* sp = pl ? cAl : cAh;                                      \
            cpa16(dbase + pl*APLB + r*144 + sg*16,                                \
                  sp + ((size_t)(row0 + r)*K)*2 + koff + sg*16);                  \
        }                                                                         \
        _Pragma("unroll")                                                         \
        for (int i = tid; i < 2048; i += 256) {                                   \
            int pl = i >> 10, r = (i >> 3) & 127, sg = i & 7;                     \
            const char* sp = pl ? cWl : cWh;                                      \
            cpa16(dbase + 2*APLB + pl*WPLB + r*144 + sg*16,                       \
                  sp + ((size_t)(col0 + r)*K)*2 + koff + sg*16);                  \
        }                                                                         \
        cpa_commit();                                                             \
    } while (0)

    LOAD_CHUNK(0, 0);

    // ldmatrix lane addressing
    const int lr  = lid & 7;
    const int lb3 = (lid >> 3) & 1;
    const int lb4 = (lid >> 4) & 1;
    uint32_t a_off[4], b_off[4];
#pragma unroll
    for (int mt = 0; mt < 4; mt++)
        a_off[mt] = (uint32_t)((wm*64 + mt*16 + lb3*8 + lr)*144 + lb4*16);
#pragma unroll
    for (int j = 0; j < 4; j++)
        b_off[j] = (uint32_t)((wn*64 + j*16 + lb4*8 + lr)*144 + lb3*16);

    float acc[4][8][4];
#pragma unroll
    for (int mt = 0; mt < 4; mt++)
#pragma unroll
        for (int nt = 0; nt < 8; nt++)
#pragma unroll
            for (int c = 0; c < 4; c++) acc[mt][nt][c] = 0.f;

    for (int kt = 0; kt < nkt; kt++) {
        const int b = kt & 1;
        if (kt + 1 < nkt) { LOAD_CHUNK(1 - b, kt + 1); cpa_wait<1>(); }
        else              { cpa_wait<0>(); }
        __syncthreads();

        const uint32_t sA = sb + b*BUFB;
        const uint32_t sW = sA + 2*APLB;

#pragma unroll
        for (int ks = 0; ks < 4; ks++) {
            const uint32_t ko = ks*32;
            uint32_t ah[4][4], bx[4][4];
            // hi x hi
#pragma unroll
            for (int mt = 0; mt < 4; mt++) ldsm4(ah[mt], sA + a_off[mt] + ko);
#pragma unroll
            for (int j = 0; j < 4; j++)    ldsm4(bx[j], sW + b_off[j] + ko);
#pragma unroll
            for (int j = 0; j < 4; j++)
#pragma unroll
                for (int jj = 0; jj < 2; jj++)
#pragma unroll
                    for (int mt = 0; mt < 4; mt++)
                        mma_bf16(acc[mt][j*2+jj], ah[mt], bx[j][jj*2], bx[j][jj*2+1]);
            // hi x lo
#pragma unroll
            for (int j = 0; j < 4; j++)    ldsm4(bx[j], sW + WPLB + b_off[j] + ko);
#pragma unroll
            for (int j = 0; j < 4; j++)
#pragma unroll
                for (int jj = 0; jj < 2; jj++)
#pragma unroll
                    for (int mt = 0; mt < 4; mt++)
                        mma_bf16(acc[mt][j*2+jj], ah[mt], bx[j][jj*2], bx[j][jj*2+1]);
            // lo x hi
#pragma unroll
            for (int mt = 0; mt < 4; mt++) ldsm4(ah[mt], sA + APLB + a_off[mt] + ko);
#pragma unroll
            for (int j = 0; j < 4; j++)    ldsm4(bx[j], sW + b_off[j] + ko);
#pragma unroll
            for (int j = 0; j < 4; j++)
#pragma unroll
                for (int jj = 0; jj < 2; jj++)
#pragma unroll
                    for (int mt = 0; mt < 4; mt++)
                        mma_bf16(acc[mt][j*2+jj], ah[mt], bx[j][jj*2], bx[j][jj*2+1]);
        }
        __syncthreads();
    }

    // ---------------- epilogue --------------------------------------------
    const float slope = (MODE == 0 || MODE == 2) ? slope_p[0] : 0.f;
    float rsl[4][2];
    if (MODE == 2) {
#pragma unroll
        for (int mt = 0; mt < 4; mt++) {
            rsl[mt][0] = rowscale[row0 + wm*64 + mt*16 + g];
            rsl[mt][1] = rowscale[row0 + wm*64 + mt*16 + g + 8];
        }
    }
    float* col_s  = (float*)smem;        // [4][128]
    float* col_q  = col_s + 512;         // [4][128]
    float* rowred = col_q + 512;         // [2][256]
    float rq[8];
#pragma unroll
    for (int i = 0; i < 8; i++) rq[i] = 0.f;
    const int pitch_u32 = Ntot >> 1;
    const int t2 = t*2;

#pragma unroll
    for (int nt = 0; nt < 8; nt++) {
        const int cl = wn*64 + nt*8 + t2;
        const int c  = col0 + cl;
        const float b0 = bias_s[cl], b1 = bias_s[cl + 1];
        float cse = 0.f, cso = 0.f, cqe = 0.f, cqo = 0.f;
#pragma unroll
        for (int mt = 0; mt < 4; mt++) {
            const int r_lo = row0 + wm*64 + mt*16 + g;
            const int r_hi = r_lo + 8;
            float v0 = acc[mt][nt][0], v1 = acc[mt][nt][1];
            float v2 = acc[mt][nt][2], v3 = acc[mt][nt][3];
            if (MODE == 2) {
                v0 = fmaf(v0, rsl[mt][0], b0); v1 = fmaf(v1, rsl[mt][0], b1);
                v2 = fmaf(v2, rsl[mt][1], b0); v3 = fmaf(v3, rsl[mt][1], b1);
            } else {
                v0 += b0; v1 += b1; v2 += b0; v3 += b1;
            }
            if (MODE == 0 || MODE == 2) {
                v0 = (v0 > 0.f) ? v0 : slope*v0;
                v1 = (v1 > 0.f) ? v1 : slope*v1;
                v2 = (v2 > 0.f) ? v2 : slope*v2;
                v3 = (v3 > 0.f) ? v3 : slope*v3;
                cse += v0 + v2; cso += v1 + v3;
                cqe += v0*v0 + v2*v2; cqo += v1*v1 + v3*v3;
            }
            if (MODE == 1) {
                rq[mt*2]   += v0*v0 + v1*v1;
                rq[mt*2+1] += v2*v2 + v3*v3;
            }
            if (MODE == 3) {
                *(float2*)&Cf[(size_t)r_lo*Ntot + c] = make_float2(v0, v1);
                *(float2*)&Cf[(size_t)r_hi*Ntot + c] = make_float2(v2, v3);
            } else {
                uint32_t h01 = cvt2bf(v1, v0);
                float h0 = __uint_as_float(h01 << 16), h1 = __uint_as_float(h01 & 0xFFFF0000u);
                uint32_t l01 = cvt2bf(v1 - h1, v0 - h0);
                uint32_t h23 = cvt2bf(v3, v2);
                float h2 = __uint_as_float(h23 << 16), h3 = __uint_as_float(h23 & 0xFFFF0000u);
                uint32_t l23 = cvt2bf(v3 - h3, v2 - h2);
                size_t i_lo = (size_t)r_lo*pitch_u32 + (c >> 1);
                size_t i_hi = (size_t)r_hi*pitch_u32 + (c >> 1);
                Ch[i_lo] = h01; Cl[i_lo] = l01;
                Ch[i_hi] = h23; Cl[i_hi] = l23;
            }
        }
        if (MODE == 0 || MODE == 2) {
#pragma unroll
            for (int o = 4; o <= 16; o <<= 1) {
                cse += __shfl_xor_sync(0xFFFFFFFFu, cse, o);
                cso += __shfl_xor_sync(0xFFFFFFFFu, cso, o);
                cqe += __shfl_xor_sync(0xFFFFFFFFu, cqe, o);
                cqo += __shfl_xor_sync(0xFFFFFFFFu, cqo, o);
            }
            if (lid < 4) {
                col_s[wm*128 + cl]     = cse;
                col_s[wm*128 + cl + 1] = cso;
                col_q[wm*128 + cl]     = cqe;
                col_q[wm*128 + cl + 1] = cqo;
            }
        }
    }
    if (MODE == 1) {
#pragma unroll
        for (int i = 0; i < 8; i++) {
            rq[i] += __shfl_xor_sync(0xFFFFFFFFu, rq[i], 1);
            rq[i] += __shfl_xor_sync(0xFFFFFFFFu, rq[i], 2);
        }
        if (t == 0) {
#pragma unroll
            for (int mt = 0; mt < 4; mt++) {
                rowred[wn*256 + wm*64 + mt*16 + g]     = rq[mt*2];
                rowred[wn*256 + wm*64 + mt*16 + g + 8] = rq[mt*2+1];
            }
        }
    }
    if (MODE == 0 || MODE == 1 || MODE == 2) {
        __syncthreads();
        if ((MODE == 0 || MODE == 2) && tid < 128) {
            float s = col_s[tid] + col_s[128 + tid] + col_s[256 + tid] + col_s[384 + tid];
            float q = col_q[tid] + col_q[128 + tid] + col_q[256 + tid] + col_q[384 + tid];
            ps[(size_t)(col0 + tid)*gridDim.y + blockIdx.y] = s;
            pq[(size_t)(col0 + tid)*gridDim.y + blockIdx.y] = q;
        }
        if (MODE == 1)
            qp[(size_t)blockIdx.x*65536 + row0 + tid] = rowred[tid] + rowred[256 + tid];
    }
}

// ===================== launch ================================================
extern "C" void kernel_launch(void* const* d_in, const int* in_sizes, int n_in,
                              void* d_out, int out_size)
{
    const float* x    = (const float*)d_in[0];
    const float* nois = (const float*)d_in[1];
    const float* W1   = (const float*)d_in[2];
    const float* b1   = (const float*)d_in[3];
    const float* a1   = (const float*)d_in[4];
    const float* g1   = (const float*)d_in[5];
    const float* bt1  = (const float*)d_in[6];
    const float* W2   = (const float*)d_in[7];
    const float* b2   = (const float*)d_in[8];
    const float* W3   = (const float*)d_in[9];
    const float* b3   = (const float*)d_in[10];
    const float* a2   = (const float*)d_in[11];
    const float* g2   = (const float*)d_in[12];
    const float* bt2  = (const float*)d_in[13];
    const float* W4   = (const float*)d_in[14];
    const float* b4   = (const float*)d_in[15];
    const float* fir  = (const float*)d_in[16];
    float* out = (float*)d_out;

    float* scr = nullptr;
    cudaGetSymbolAddress((void**)&scr, g_scratch);
    uint32_t* XH = (uint32_t*)(scr + U_XH);  uint32_t* XL = (uint32_t*)(scr + U_XL);
    uint32_t* TH = (uint32_t*)(scr + U_TH);  uint32_t* TL = (uint32_t*)(scr + U_TL);
    uint32_t* YH = (uint32_t*)(scr + U_YH);  uint32_t* YL = (uint32_t*)(scr + U_YL);
    float* S  = scr + U_S;
    float* PS = scr + U_PS;  float* PQ = scr + U_PQ;  float* QP = scr + U_QP;
    float* AL = scr + U_AL;  float* BE = scr + U_BE;
    uint32_t* W1H = (uint32_t*)(scr + U_W1H); uint32_t* W1L = (uint32_t*)(scr + U_W1L);
    uint32_t* W2H = (uint32_t*)(scr + U_W2H); uint32_t* W2L = (uint32_t*)(scr + U_W2L);
    uint32_t* W3H = (uint32_t*)(scr + U_W3H); uint32_t* W3L = (uint32_t*)(scr + U_W3L);
    uint32_t* W4H = (uint32_t*)(scr + U_W4H); uint32_t* W4L = (uint32_t*)(scr + U_W4L);
    float* B2F = scr + U_B2F; float* C3 = scr + U_C3;
    float* NC  = scr + U_NC;  float* B4F = scr + U_B4F;

    cudaFuncSetAttribute(gemm_hmma<0>, cudaFuncAttributeMaxDynamicSharedMemorySize, SMEMSZ);
    cudaFuncSetAttribute(gemm_hmma<1>, cudaFuncAttributeMaxDynamicSharedMemorySize, SMEMSZ);
    cudaFuncSetAttribute(gemm_hmma<2>, cudaFuncAttributeMaxDynamicSharedMemorySize, SMEMSZ);
    cudaFuncSetAttribute(gemm_hmma<3>, cudaFuncAttributeMaxDynamicSharedMemorySize, SMEMSZ);

    long long need = (long long)BSZ*512 + 256;
    float* tail = ((long long)out_size >= need) ? out + (out_size - 256) : nullptr;

    // independent prep
    k_noise<<<1, 256>>>(nois, fir, NC, tail);
    k_split4<<<2048, 256>>>((const float4*)x,  nullptr, (uint2*)XH, (uint2*)XL, 8388608, 511);
    k_split4<<<64, 256>>>((const float4*)W1, nullptr, (uint2*)W1H, (uint2*)W1L, 65536, 511);
    k_split4<<<32, 256>>>((const float4*)W3, nullptr, (uint2*)W3H, (uint2*)W3L, 32768, 255);

    // stage 1: t = prelu(x@W1^T + b1) ; col stats in epilogue
    gemm_hmma<0><<<dim3(4, 256), 256, SMEMSZ>>>(
        XH, XL, W1H, W1L, b1, TH, TL, nullptr, nullptr, a1, PS, PQ, nullptr, 512, 512);
    k_affine<<<512, 128>>>(PS, PQ, g1, bt1, AL, BE, 256);
    k_split4<<<32, 256>>>((const float4*)W2, AL, (uint2*)W2H, (uint2*)W2L, 32768, 511);
    k_fold_b<<<256, 128>>>(W2, BE, b2, B2F, 512);

    // stage 2: y = t_bn @ W2f^T + b2f ; row sumsq partials
    gemm_hmma<1><<<dim3(2, 256), 256, SMEMSZ>>>(
        TH, TL, W2H, W2L, B2F, YH, YL, nullptr, nullptr, nullptr, nullptr, nullptr, QP, 512, 256);
    k_scale<<<256, 256>>>(QP, S);
    k_fold_b<<<512, 128>>>(W3, NC, b3, C3, 256);

    // stage 3: d = prelu(s_i*(y@W3^T) + c3) ; col stats (d reuses x planes)
    gemm_hmma<2><<<dim3(4, 256), 256, SMEMSZ>>>(
        YH, YL, W3H, W3L, C3, XH, XL, nullptr, S, a2, PS, PQ, nullptr, 256, 512);
    k_affine<<<512, 128>>>(PS, PQ, g2, bt2, AL, BE, 256);
    k_split4<<<64, 256>>>((const float4*)W4, AL, (uint2*)W4H, (uint2*)W4L, 65536, 511);
    k_fold_b<<<512, 128>>>(W4, BE, b4, B4F, 512);

    // stage 4: out = d_bn @ W4f^T + b4f (fp32)
    gemm_hmma<3><<<dim3(4, 256), 256, SMEMSZ>>>(
        XH, XL, W4H, W4L, B4F, nullptr, nullptr, out, nullptr, nullptr,
        nullptr, nullptr, nullptr, 512, 512);
}

// round 8
// speedup vs baseline: 2.6370x; 1.0079x over previous
#include <cuda_runtime.h>
#include <math.h>
#include <stdint.h>

#define BSZ  65536
#define EPSf 1e-5f

// ===================== scratch layout (4-byte units) ========================
#define U_XH  0ull
#define U_XL  (U_XH  + 16777216ull)
#define U_TH  (U_XL  + 16777216ull)
#define U_TL  (U_TH  + 16777216ull)
#define U_YH  (U_TL  + 16777216ull)
#define U_YL  (U_YH  + 8388608ull)
#define U_S   (U_YL  + 8388608ull)
#define U_PS  (U_S   + 65536ull)
#define U_PQ  (U_PS  + 262144ull)
#define U_QP  (U_PQ  + 262144ull)
#define U_AL  (U_QP  + 131072ull)
#define U_BE  (U_AL  + 512ull)
#define U_W1H (U_BE  + 512ull)
#define U_W1L (U_W1H + 131072ull)
#define U_W2H (U_W1L + 131072ull)
#define U_W2L (U_W2H + 65536ull)
#define U_W3H (U_W2L + 65536ull)
#define U_W3L (U_W3H + 65536ull)
#define U_W4H (U_W3L + 65536ull)
#define U_W4L (U_W4H + 131072ull)
#define U_B2F (U_W4L + 131072ull)
#define U_C3  (U_B2F + 256ull)
#define U_NC  (U_C3  + 512ull)
#define U_B4F (U_NC  + 256ull)
#define U_TOT (U_B4F + 512ull)

__device__ __align__(1024) float g_scratch[U_TOT];

// ===================== helpers ==============================================
__device__ __forceinline__ uint32_t smem_u32(const void* p) {
    uint32_t a;
    asm("{ .reg .u64 t; cvta.to.shared.u64 t, %1; cvt.u32.u64 %0, t; }" : "=r"(a) : "l"(p));
    return a;
}
__device__ __forceinline__ void cpa16(uint32_t dst, const void* src) {
    asm volatile("cp.async.cg.shared.global [%0], [%1], 16;" :: "r"(dst), "l"(src) : "memory");
}
__device__ __forceinline__ void cpa_commit() {
    asm volatile("cp.async.commit_group;" ::: "memory");
}
template<int N> __device__ __forceinline__ void cpa_wait() {
    asm volatile("cp.async.wait_group %0;" :: "n"(N) : "memory");
}
__device__ __forceinline__ void ldsm4(uint32_t* r, uint32_t addr) {
    asm volatile("ldmatrix.sync.aligned.m8n8.x4.shared.b16 {%0,%1,%2,%3}, [%4];"
        : "=r"(r[0]), "=r"(r[1]), "=r"(r[2]), "=r"(r[3]) : "r"(addr));
}
__device__ __forceinline__ void mma_bf16(float* d, const uint32_t* a, uint32_t b0, uint32_t b1) {
    asm volatile("mma.sync.aligned.m16n8k16.row.col.f32.bf16.bf16.f32 "
        "{%0,%1,%2,%3}, {%4,%5,%6,%7}, {%8,%9}, {%0,%1,%2,%3};"
        : "+f"(d[0]), "+f"(d[1]), "+f"(d[2]), "+f"(d[3])
        : "r"(a[0]), "r"(a[1]), "r"(a[2]), "r"(a[3]), "r"(b0), "r"(b1));
}
__device__ __forceinline__ uint32_t cvt2bf(float hi, float lo) {
    uint32_t r;
    asm("cvt.rn.bf16x2.f32 %0, %1, %2;" : "=r"(r) : "f"(hi), "f"(lo));
    return r;
}

// ===================== small kernels ========================================
__global__ void k_noise(const float* __restrict__ noise, const float* __restrict__ fir,
                        float* __restrict__ nc_out, float* __restrict__ tail)
{
    __shared__ float v[256];
    int t = threadIdx.x;
    float nstd = (float)sqrt(1.0 / (4.0 * pow(10.0, 0.7)));
    v[t] = noise[t] * nstd;
    __syncthreads();
    float acc = 0.f;
#pragma unroll
    for (int j = 0; j < 100; j++) {
        int idx = t + 49 - j;
        if (idx >= 0 && idx < 256) acc = fmaf(fir[j], v[idx], acc);
    }
    nc_out[t] = acc;
    if (tail) tail[t] = acc;
}

__global__ void k_split4(const float4* __restrict__ W, const float* __restrict__ alpha,
                         uint2* __restrict__ Ph, uint2* __restrict__ Pl,
                         int total4, int kmask)
{
    for (int i = blockIdx.x*blockDim.x + threadIdx.x; i < total4; i += gridDim.x*blockDim.x) {
        float4 v = W[i];
        if (alpha) {
            int k = (4*i) & kmask;
            v.x *= alpha[k]; v.y *= alpha[k+1]; v.z *= alpha[k+2]; v.w *= alpha[k+3];
        }
        uint32_t h0 = cvt2bf(v.y, v.x), h1 = cvt2bf(v.w, v.z);
        float a0 = __uint_as_float(h0 << 16), a1 = __uint_as_float(h0 & 0xFFFF0000u);
        float a2 = __uint_as_float(h1 << 16), a3 = __uint_as_float(h1 & 0xFFFF0000u);
        uint32_t l0 = cvt2bf(v.y - a1, v.x - a0), l1 = cvt2bf(v.w - a3, v.z - a2);
        Ph[i] = make_uint2(h0, h1);
        Pl[i] = make_uint2(l0, l1);
    }
}

__global__ void k_affine(const float* __restrict__ ps, const float* __restrict__ pq,
                         const float* __restrict__ g, const float* __restrict__ bt,
                         float* __restrict__ alpha, float* __restrict__ beta, int np)
{
    int j = blockIdx.x, t = threadIdx.x;   // 128 threads
    float s = 0.f, q = 0.f;
    for (int i = t; i < np; i += 128) { s += ps[j*np + i]; q += pq[j*np + i]; }
    __shared__ float rs[128], rq[128];
    rs[t] = s; rq[t] = q; __syncthreads();
    for (int o = 64; o > 0; o >>= 1) {
        if (t < o) { rs[t] += rs[t+o]; rq[t] += rq[t+o]; }
        __syncthreads();
    }
    if (t == 0) {
        float mu  = rs[0] * (1.f/65536.f);
        float var = rq[0] * (1.f/65536.f) - mu*mu;
        float a = g[j] * rsqrtf(var + EPSf);
        alpha[j] = a; beta[j] = bt[j] - mu*a;
    }
}

__global__ void k_scale(const float* __restrict__ qp, float* __restrict__ s)
{
    int r = blockIdx.x*256 + threadIdx.x;
    s[r] = sqrtf(256.f / (qp[r] + qp[65536 + r]));
}

__global__ void k_fold_b(const float* __restrict__ W, const float* __restrict__ beta,
                         const float* __restrict__ b, float* __restrict__ bf, int K)
{
    int j = blockIdx.x, t = threadIdx.x;
    float acc = 0.f;
    for (int k = t; k < K; k += 128) acc += beta[k] * W[(size_t)j*K + k];
    __shared__ float r[128];
    r[t] = acc; __syncthreads();
    for (int o = 64; o > 0; o >>= 1) { if (t < o) r[t] += r[t+o]; __syncthreads(); }
    if (t == 0) bf[j] = b[j] + r[0];
}

// ===================== HMMA GEMM ============================================
// C[M,N] = epi( A[M,K] @ W[N,K]^T + bias )
// BM=256 BN=128 KC=64, 256 threads, 8 warps (4M x 2N), warp tile 64x64
// MODE 0: +bias, prelu, store planes, col stats partials
// MODE 1: +bias, store planes, row sumsq partials
// MODE 2: rowscale*acc + bias, prelu, store planes, col stats partials
// MODE 3: +bias, store fp32
#define APLB   36864            // A plane bytes: 256 rows * 144
#define WPLB   18432            // W plane bytes: 128 rows * 144
#define BUFB   (2*APLB + 2*WPLB)
#define SMEMSZ (2*BUFB)

template<int MODE>
__global__ void __launch_bounds__(256, 1)
gemm_hmma(const uint32_t* __restrict__ Ah, const uint32_t* __restrict__ Al,
          const uint32_t* __restrict__ Wh, const uint32_t* __restrict__ Wl,
          const float* __restrict__ bias,
          uint32_t* __restrict__ Ch, uint32_t* __restrict__ Cl, float* __restrict__ Cf,
          const float* __restrict__ rowscale, const float* __restrict__ slope_p,
          float* __restrict__ ps, float* __restrict__ pq, float* __restrict__ qp,
          int K, int Ntot)
{
    extern __shared__ __align__(1024) char smem[];
    __shared__ float bias_s[128];
    const uint32_t sb = smem_u32(smem);
    const int tid = threadIdx.x;
    const int wid = tid >> 5, lid = tid & 31;
    const int wm = wid & 3, wn = wid >> 2;
    const int g = lid >> 2, t = lid & 3;
    const int row0 = blockIdx.y * 256;
    const int col0 = blockIdx.x * 128;
    const int nkt = K >> 6;

    if (tid < 128) bias_s[tid] = bias[col0 + tid];

    // chunk loader: 6144 cp.async of 16B
    const char* cAh = (const char*)Ah;  const char* cAl = (const char*)Al;
    const char* cWh = (const char*)Wh;  const char* cWl = (const char*)Wl;

#define LOAD_CHUNK(BUF, KT)                                                       \
    do {                                                                          \
        uint32_t dbase = sb + (BUF)*BUFB;                                         \
        size_t koff = (size_t)(KT)*64*2;                                          \
        _Pragma("unroll")                                                         \
        for (int i = tid; i < 4096; i += 256) {                                   \
            int pl = i >> 11, r = (i >> 3) & 255, sg = i & 7;                     \
            const char* sp = pl ? cAl : cAh;                                      \
            cpa16(dbase + pl*APLB + r*144 + sg*16,                                \
                  sp + ((size_t)(row0 + r)*K)*2 + koff + sg*16);                  \
        }                                                                         \
        _Pragma("unroll")                                                         \
        for (int i = tid; i < 2048; i += 256) {                                   \
            int pl = i >> 10, r = (i >> 3) & 127, sg = i & 7;                     \
            const char* sp = pl ? cWl : cWh;                                      \
            cpa16(dbase + 2*APLB + pl*WPLB + r*144 + sg*16,                       \
                  sp + ((size_t)(col0 + r)*K)*2 + koff + sg*16);                  \
        }                                                                         \
        cpa_commit();                                                             \
    } while (0)

    LOAD_CHUNK(0, 0);

    // ldmatrix lane addressing
    const int lr  = lid & 7;
    const int lb3 = (lid >> 3) & 1;
    const int lb4 = (lid >> 4) & 1;
    uint32_t a_off[4], b_off[4];
#pragma unroll
    for (int mt = 0; mt < 4; mt++)
        a_off[mt] = (uint32_t)((wm*64 + mt*16 + lb3*8 + lr)*144 + lb4*16);
#pragma unroll
    for (int j = 0; j < 4; j++)
        b_off[j] = (uint32_t)((wn*64 + j*16 + lb4*8 + lr)*144 + lb3*16);

    float acc[4][8][4];
#pragma unroll
    for (int mt = 0; mt < 4; mt++)
#pragma unroll
        for (int nt = 0; nt < 8; nt++)
#pragma unroll
            for (int c = 0; c < 4; c++) acc[mt][nt][c] = 0.f;

    for (int kt = 0; kt < nkt; kt++) {
        const int b = kt & 1;
        if (kt + 1 < nkt) { LOAD_CHUNK(1 - b, kt + 1); cpa_wait<1>(); }
        else              { cpa_wait<0>(); }
        __syncthreads();

        const uint32_t sA = sb + b*BUFB;
        const uint32_t sW = sA + 2*APLB;

#pragma unroll
        for (int ks = 0; ks < 4; ks++) {
            const uint32_t ko = ks*32;
            uint32_t ah[4][4], bx[4][4];
            // hi x hi
#pragma unroll
            for (int mt = 0; mt < 4; mt++) ldsm4(ah[mt], sA + a_off[mt] + ko);
#pragma unroll
            for (int j = 0; j < 4; j++)    ldsm4(bx[j], sW + b_off[j] + ko);
#pragma unroll
            for (int j = 0; j < 4; j++)
#pragma unroll
                for (int jj = 0; jj < 2; jj++)
#pragma unroll
                    for (int mt = 0; mt < 4; mt++)
                        mma_bf16(acc[mt][j*2+jj], ah[mt], bx[j][jj*2], bx[j][jj*2+1]);
            // hi x lo
#pragma unroll
            for (int j = 0; j < 4; j++)    ldsm4(bx[j], sW + WPLB + b_off[j] + ko);
#pragma unroll
            for (int j = 0; j < 4; j++)
#pragma unroll
                for (int jj = 0; jj < 2; jj++)
#pragma unroll
                    for (int mt = 0; mt < 4; mt++)
                        mma_bf16(acc[mt][j*2+jj], ah[mt], bx[j][jj*2], bx[j][jj*2+1]);
            // lo x hi
#pragma unroll
            for (int mt = 0; mt < 4; mt++) ldsm4(ah[mt], sA + APLB + a_off[mt] + ko);
#pragma unroll
            for (int j = 0; j < 4; j++)    ldsm4(bx[j], sW + b_off[j] + ko);
#pragma unroll
            for (int j = 0; j < 4; j++)
#pragma unroll
                for (int jj = 0; jj < 2; jj++)
#pragma unroll
                    for (int mt = 0; mt < 4; mt++)
                        mma_bf16(acc[mt][j*2+jj], ah[mt], bx[j][jj*2], bx[j][jj*2+1]);
        }
        __syncthreads();
    }

    // ---------------- epilogue --------------------------------------------
    const float slope = (MODE == 0 || MODE == 2) ? slope_p[0] : 0.f;
    float rsl[4][2];
    if (MODE == 2) {
#pragma unroll
        for (int mt = 0; mt < 4; mt++) {
            rsl[mt][0] = rowscale[row0 + wm*64 + mt*16 + g];
            rsl[mt][1] = rowscale[row0 + wm*64 + mt*16 + g + 8];
        }
    }
    float* col_s  = (float*)smem;        // [4][128]
    float* col_q  = col_s + 512;         // [4][128]
    float* rowred = col_q + 512;         // [2][256]
    float rq[8];
#pragma unroll
    for (int i = 0; i < 8; i++) rq[i] = 0.f;
    const int pitch_u32 = Ntot >> 1;
    const int t2 = t*2;

#pragma unroll
    for (int nt = 0; nt < 8; nt++) {
        const int cl = wn*64 + nt*8 + t2;
        const int c  = col0 + cl;
        const float b0 = bias_s[cl], b1 = bias_s[cl + 1];
        float cse = 0.f, cso = 0.f, cqe = 0.f, cqo = 0.f;
#pragma unroll
        for (int mt = 0; mt < 4; mt++) {
            const int r_lo = row0 + wm*64 + mt*16 + g;
            const int r_hi = r_lo + 8;
            float v0 = acc[mt][nt][0], v1 = acc[mt][nt][1];
            float v2 = acc[mt][nt][2], v3 = acc[mt][nt][3];
            if (MODE == 2) {
                v0 = fmaf(v0, rsl[mt][0], b0); v1 = fmaf(v1, rsl[mt][0], b1);
                v2 = fmaf(v2, rsl[mt][1], b0); v3 = fmaf(v3, rsl[mt][1], b1);
            } else {
                v0 += b0; v1 += b1; v2 += b0; v3 += b1;
            }
            if (MODE == 0 || MODE == 2) {
                v0 = (v0 > 0.f) ? v0 : slope*v0;
                v1 = (v1 > 0.f) ? v1 : slope*v1;
                v2 = (v2 > 0.f) ? v2 : slope*v2;
                v3 = (v3 > 0.f) ? v3 : slope*v3;
                cse += v0 + v2; cso += v1 + v3;
                cqe += v0*v0 + v2*v2; cqo += v1*v1 + v3*v3;
            }
            if (MODE == 1) {
                rq[mt*2]   += v0*v0 + v1*v1;
                rq[mt*2+1] += v2*v2 + v3*v3;
            }
            if (MODE == 3) {
                *(float2*)&Cf[(size_t)r_lo*Ntot + c] = make_float2(v0, v1);
                *(float2*)&Cf[(size_t)r_hi*Ntot + c] = make_float2(v2, v3);
            } else {
                uint32_t h01 = cvt2bf(v1, v0);
                float h0 = __uint_as_float(h01 << 16), h1 = __uint_as_float(h01 & 0xFFFF0000u);
                uint32_t l01 = cvt2bf(v1 - h1, v0 - h0);
                uint32_t h23 = cvt2bf(v3, v2);
                float h2 = __uint_as_float(h23 << 16), h3 = __uint_as_float(h23 & 0xFFFF0000u);
                uint32_t l23 = cvt2bf(v3 - h3, v2 - h2);
                size_t i_lo = (size_t)r_lo*pitch_u32 + (c >> 1);
                size_t i_hi = (size_t)r_hi*pitch_u32 + (c >> 1);
                Ch[i_lo] = h01; Cl[i_lo] = l01;
                Ch[i_hi] = h23; Cl[i_hi] = l23;
            }
        }
        if (MODE == 0 || MODE == 2) {
#pragma unroll
            for (int o = 4; o <= 16; o <<= 1) {
                cse += __shfl_xor_sync(0xFFFFFFFFu, cse, o);
                cso += __shfl_xor_sync(0xFFFFFFFFu, cso, o);
                cqe += __shfl_xor_sync(0xFFFFFFFFu, cqe, o);
                cqo += __shfl_xor_sync(0xFFFFFFFFu, cqo, o);
            }
            if (lid < 4) {
                col_s[wm*128 + cl]     = cse;
                col_s[wm*128 + cl + 1] = cso;
                col_q[wm*128 + cl]     = cqe;
                col_q[wm*128 + cl + 1] = cqo;
            }
        }
    }
    if (MODE == 1) {
#pragma unroll
        for (int i = 0; i < 8; i++) {
            rq[i] += __shfl_xor_sync(0xFFFFFFFFu, rq[i], 1);
            rq[i] += __shfl_xor_sync(0xFFFFFFFFu, rq[i], 2);
        }
        if (t == 0) {
#pragma unroll
            for (int mt = 0; mt < 4; mt++) {
                rowred[wn*256 + wm*64 + mt*16 + g]     = rq[mt*2];
                rowred[wn*256 + wm*64 + mt*16 + g + 8] = rq[mt*2+1];
            }
        }
    }
    if (MODE == 0 || MODE == 1 || MODE == 2) {
        __syncthreads();
        if ((MODE == 0 || MODE == 2) && tid < 128) {
            float s = col_s[tid] + col_s[128 + tid] + col_s[256 + tid] + col_s[384 + tid];
            float q = col_q[tid] + col_q[128 + tid] + col_q[256 + tid] + col_q[384 + tid];
            ps[(size_t)(col0 + tid)*gridDim.y + blockIdx.y] = s;
            pq[(size_t)(col0 + tid)*gridDim.y + blockIdx.y] = q;
        }
        if (MODE == 1)
            qp[(size_t)blockIdx.x*65536 + row0 + tid] = rowred[tid] + rowred[256 + tid];
    }
}

// ===================== launch ================================================
extern "C" void kernel_launch(void* const* d_in, const int* in_sizes, int n_in,
                              void* d_out, int out_size)
{
    const float* x    = (const float*)d_in[0];
    const float* nois = (const float*)d_in[1];
    const float* W1   = (const float*)d_in[2];
    const float* b1   = (const float*)d_in[3];
    const float* a1   = (const float*)d_in[4];
    const float* g1   = (const float*)d_in[5];
    const float* bt1  = (const float*)d_in[6];
    const float* W2   = (const float*)d_in[7];
    const float* b2   = (const float*)d_in[8];
    const float* W3   = (const float*)d_in[9];
    const float* b3   = (const float*)d_in[10];
    const float* a2   = (const float*)d_in[11];
    const float* g2   = (const float*)d_in[12];
    const float* bt2  = (const float*)d_in[13];
    const float* W4   = (const float*)d_in[14];
    const float* b4   = (const float*)d_in[15];
    const float* fir  = (const float*)d_in[16];
    float* out = (float*)d_out;

    float* scr = nullptr;
    cudaGetSymbolAddress((void**)&scr, g_scratch);
    uint32_t* XH = (uint32_t*)(scr + U_XH);  uint32_t* XL = (uint32_t*)(scr + U_XL);
    uint32_t* TH = (uint32_t*)(scr + U_TH);  uint32_t* TL = (uint32_t*)(scr + U_TL);
    uint32_t* YH = (uint32_t*)(scr + U_YH);  uint32_t* YL = (uint32_t*)(scr + U_YL);
    float* S  = scr + U_S;
    float* PS = scr + U_PS;  float* PQ = scr + U_PQ;  float* QP = scr + U_QP;
    float* AL = scr + U_AL;  float* BE = scr + U_BE;
    uint32_t* W1H = (uint32_t*)(scr + U_W1H); uint32_t* W1L = (uint32_t*)(scr + U_W1L);
    uint32_t* W2H = (uint32_t*)(scr + U_W2H); uint32_t* W2L = (uint32_t*)(scr + U_W2L);
    uint32_t* W3H = (uint32_t*)(scr + U_W3H); uint32_t* W3L = (uint32_t*)(scr + U_W3L);
    uint32_t* W4H = (uint32_t*)(scr + U_W4H); uint32_t* W4L = (uint32_t*)(scr + U_W4L);
    float* B2F = scr + U_B2F; float* C3 = scr + U_C3;
    float* NC  = scr + U_NC;  float* B4F = scr + U_B4F;

    cudaFuncSetAttribute(gemm_hmma<0>, cudaFuncAttributeMaxDynamicSharedMemorySize, SMEMSZ);
    cudaFuncSetAttribute(gemm_hmma<1>, cudaFuncAttributeMaxDynamicSharedMemorySize, SMEMSZ);
    cudaFuncSetAttribute(gemm_hmma<2>, cudaFuncAttributeMaxDynamicSharedMemorySize, SMEMSZ);
    cudaFuncSetAttribute(gemm_hmma<3>, cudaFuncAttributeMaxDynamicSharedMemorySize, SMEMSZ);

    long long need = (long long)BSZ*512 + 256;
    float* tail = ((long long)out_size >= need) ? out + (out_size - 256) : nullptr;

    // independent prep
    k_noise<<<1, 256>>>(nois, fir, NC, tail);
    k_split4<<<2048, 256>>>((const float4*)x,  nullptr, (uint2*)XH, (uint2*)XL, 8388608, 511);
    k_split4<<<64, 256>>>((const float4*)W1, nullptr, (uint2*)W1H, (uint2*)W1L, 65536, 511);
    k_split4<<<32, 256>>>((const float4*)W3, nullptr, (uint2*)W3H, (uint2*)W3L, 32768, 255);

    // stage 1: t = prelu(x@W1^T + b1) ; col stats in epilogue
    gemm_hmma<0><<<dim3(4, 256), 256, SMEMSZ>>>(
        XH, XL, W1H, W1L, b1, TH, TL, nullptr, nullptr, a1, PS, PQ, nullptr, 512, 512);
    k_affine<<<512, 128>>>(PS, PQ, g1, bt1, AL, BE, 256);
    k_split4<<<32, 256>>>((const float4*)W2, AL, (uint2*)W2H, (uint2*)W2L, 32768, 511);
    k_fold_b<<<256, 128>>>(W2, BE, b2, B2F, 512);

    // stage 2: y = t_bn @ W2f^T + b2f ; row sumsq partials
    gemm_hmma<1><<<dim3(2, 256), 256, SMEMSZ>>>(
        TH, TL, W2H, W2L, B2F, YH, YL, nullptr, nullptr, nullptr, nullptr, nullptr, QP, 512, 256);
    k_scale<<<256, 256>>>(QP, S);
    k_fold_b<<<512, 128>>>(W3, NC, b3, C3, 256);

    // stage 3: d = prelu(s_i*(y@W3^T) + c3) ; col stats (d reuses x planes)
    gemm_hmma<2><<<dim3(4, 256), 256, SMEMSZ>>>(
        YH, YL, W3H, W3L, C3, XH, XL, nullptr, S, a2, PS, PQ, nullptr, 256, 512);
    k_affine<<<512, 128>>>(PS, PQ, g2, bt2, AL, BE, 256);
    k_split4<<<64, 256>>>((const float4*)W4, AL, (uint2*)W4H, (uint2*)W4L, 65536, 511);
    k_fold_b<<<512, 128>>>(W4, BE, b4, B4F, 512);

    // stage 4: out = d_bn @ W4f^T + b4f (fp32)
    gemm_hmma<3><<<dim3(4, 256), 256, SMEMSZ>>>(
        XH, XL, W4H, W4L, B4F, nullptr, nullptr, out, nullptr, nullptr,
        nullptr, nullptr, nullptr, 512, 512);
}